// round 1
// baseline (speedup 1.0000x reference)
#include <cuda_runtime.h>
#include <cstdint>

// Problem dims
#define B_DIM   16384
#define K_DIM   6144          // 48 features * 128 embed
#define N_DIM   1024
#define EMB     128
#define N_WORD_F 18
#define N_TAG_F  18
// deprel: 12

// Scratch for hidden activations h = relu(x @ W_h + b_h): 16384 x 1024 fp32 = 64 MB
__device__ float g_h[(size_t)B_DIM * N_DIM];

// ---------------------------------------------------------------------------
// GEMM1: h = relu(gather(x) @ W_h + b_h)
// Tile: BM=128, BN=128, BK=16. 256 threads, 8x8 per-thread microtile.
// A (gathered) stored transposed in smem As[k][m] (stride 132 to dodge conflicts).
// ---------------------------------------------------------------------------
__device__ __forceinline__ const float* gather_row_ptr(
    int gm, int f,
    const int* __restrict__ wid, const int* __restrict__ tgid, const int* __restrict__ did,
    const float* __restrict__ wemb, const float* __restrict__ temb, const float* __restrict__ demb)
{
    if (f < N_WORD_F) {
        int id = wid[gm * N_WORD_F + f];
        return wemb + (size_t)id * EMB;
    } else if (f < N_WORD_F + N_TAG_F) {
        int id = tgid[gm * N_TAG_F + (f - N_WORD_F)];
        return temb + (size_t)id * EMB;
    } else {
        int id = did[gm * 12 + (f - N_WORD_F - N_TAG_F)];
        return demb + (size_t)id * EMB;
    }
}

__global__ __launch_bounds__(256, 2)
void gemm1_kernel(const int* __restrict__ wid, const int* __restrict__ tgid,
                  const int* __restrict__ did,
                  const float* __restrict__ wemb, const float* __restrict__ temb,
                  const float* __restrict__ demb,
                  const float* __restrict__ Wh, const float* __restrict__ bh)
{
    __shared__ float As[2][16 * 132];
    __shared__ float Bs[2][16 * 132];

    const int t  = threadIdx.x;
    const int tx = t & 15;        // N direction (8 cols each)
    const int ty = t >> 4;        // M direction (8 rows each)
    const int m_blk = blockIdx.y * 128;
    const int n0    = blockIdx.x * 128;

    float acc[8][8];
#pragma unroll
    for (int i = 0; i < 8; ++i)
#pragma unroll
        for (int j = 0; j < 8; ++j) acc[i][j] = 0.0f;

    // A staging: 128 rows x 16 k = 512 float4 (along k), 2 per thread
    const int av0 = t, av1 = t + 256;
    const int am0 = av0 >> 2, akq0 = av0 & 3;
    const int am1 = av1 >> 2, akq1 = av1 & 3;
    const int gm0 = m_blk + am0;
    const int gm1 = m_blk + am1;

    // B staging: 16 k x 128 n = 512 float4 (along n), 2 per thread
    const int bkk0 = av0 >> 5, bnq0 = av0 & 31;
    const int bkk1 = av1 >> 5, bnq1 = av1 & 31;

    float4 ra0, ra1, rb0, rb1;

    auto load_tile = [&](int kt) {
        const int f  = kt >> 3;            // 8 k-tiles of 16 per 128-wide feature
        const int kc = (kt & 7) << 4;      // column offset within the embedding row
        const float* r0 = gather_row_ptr(gm0, f, wid, tgid, did, wemb, temb, demb);
        const float* r1 = gather_row_ptr(gm1, f, wid, tgid, did, wemb, temb, demb);
        ra0 = *(const float4*)(r0 + kc + (akq0 << 2));
        ra1 = *(const float4*)(r1 + kc + (akq1 << 2));
        const float* wb = Wh + (size_t)(kt * 16) * N_DIM + n0;
        rb0 = *(const float4*)(wb + (size_t)bkk0 * N_DIM + (bnq0 << 2));
        rb1 = *(const float4*)(wb + (size_t)bkk1 * N_DIM + (bnq1 << 2));
    };

    auto store_tile = [&](int buf) {
        float* a = As[buf];
        a[(akq0 * 4 + 0) * 132 + am0] = ra0.x;
        a[(akq0 * 4 + 1) * 132 + am0] = ra0.y;
        a[(akq0 * 4 + 2) * 132 + am0] = ra0.z;
        a[(akq0 * 4 + 3) * 132 + am0] = ra0.w;
        a[(akq1 * 4 + 0) * 132 + am1] = ra1.x;
        a[(akq1 * 4 + 1) * 132 + am1] = ra1.y;
        a[(akq1 * 4 + 2) * 132 + am1] = ra1.z;
        a[(akq1 * 4 + 3) * 132 + am1] = ra1.w;
        *(float4*)&Bs[buf][bkk0 * 132 + (bnq0 << 2)] = rb0;
        *(float4*)&Bs[buf][bkk1 * 132 + (bnq1 << 2)] = rb1;
    };

    const int NKT = K_DIM / 16;  // 384
    load_tile(0);
    store_tile(0);
    __syncthreads();

    int buf = 0;
    for (int kt = 0; kt < NKT; ++kt) {
        if (kt + 1 < NKT) load_tile(kt + 1);

        const float* ap = As[buf];
        const float* bp = Bs[buf];
#pragma unroll
        for (int kk = 0; kk < 16; ++kk) {
            float a[8], b[8];
            *(float4*)&a[0] = *(const float4*)&ap[kk * 132 + ty * 8];
            *(float4*)&a[4] = *(const float4*)&ap[kk * 132 + ty * 8 + 4];
            *(float4*)&b[0] = *(const float4*)&bp[kk * 132 + tx * 8];
            *(float4*)&b[4] = *(const float4*)&bp[kk * 132 + tx * 8 + 4];
#pragma unroll
            for (int i = 0; i < 8; ++i)
#pragma unroll
                for (int j = 0; j < 8; ++j)
                    acc[i][j] = fmaf(a[i], b[j], acc[i][j]);
        }

        if (kt + 1 < NKT) {
            store_tile(buf ^ 1);
            __syncthreads();
            buf ^= 1;
        }
    }

    // Epilogue: + b_h, relu, write h
    float bias[8];
#pragma unroll
    for (int j = 0; j < 8; ++j) bias[j] = bh[n0 + tx * 8 + j];

#pragma unroll
    for (int i = 0; i < 8; ++i) {
        const int row = m_blk + ty * 8 + i;
        float v[8];
#pragma unroll
        for (int j = 0; j < 8; ++j) {
            float x = acc[i][j] + bias[j];
            v[j] = x > 0.0f ? x : 0.0f;
        }
        float* hp = g_h + (size_t)row * N_DIM + n0 + tx * 8;
        *(float4*)(hp)     = make_float4(v[0], v[1], v[2], v[3]);
        *(float4*)(hp + 4) = make_float4(v[4], v[5], v[6], v[7]);
    }
}

// ---------------------------------------------------------------------------
// GEMM2: out = h @ W_o + b_o   (N=3). One warp per row, fully coalesced h reads.
// ---------------------------------------------------------------------------
__global__ __launch_bounds__(256)
void gemm2_kernel(const float* __restrict__ Wo, const float* __restrict__ bo,
                  float* __restrict__ out)
{
    __shared__ float w[3][N_DIM];   // transposed W_o
    const int t = threadIdx.x;
    for (int i = t; i < 3 * N_DIM; i += 256) {
        int c = i / N_DIM;
        int n = i - c * N_DIM;
        w[c][n] = Wo[n * 3 + c];
    }
    __syncthreads();

    const int warp = t >> 5;
    const int lane = t & 31;
    const int row  = blockIdx.x * 8 + warp;

    const float* hp = g_h + (size_t)row * N_DIM;
    float s0 = 0.0f, s1 = 0.0f, s2 = 0.0f;
#pragma unroll
    for (int it = 0; it < 8; ++it) {
        const int n = it * 128 + lane * 4;
        float4 hv = *(const float4*)(hp + n);
        s0 += hv.x * w[0][n] + hv.y * w[0][n + 1] + hv.z * w[0][n + 2] + hv.w * w[0][n + 3];
        s1 += hv.x * w[1][n] + hv.y * w[1][n + 1] + hv.z * w[1][n + 2] + hv.w * w[1][n + 3];
        s2 += hv.x * w[2][n] + hv.y * w[2][n + 1] + hv.z * w[2][n + 2] + hv.w * w[2][n + 3];
    }
#pragma unroll
    for (int o = 16; o; o >>= 1) {
        s0 += __shfl_xor_sync(0xffffffffu, s0, o);
        s1 += __shfl_xor_sync(0xffffffffu, s1, o);
        s2 += __shfl_xor_sync(0xffffffffu, s2, o);
    }
    if (lane == 0) {
        out[row * 3 + 0] = s0 + bo[0];
        out[row * 3 + 1] = s1 + bo[1];
        out[row * 3 + 2] = s2 + bo[2];
    }
}

extern "C" void kernel_launch(void* const* d_in, const int* in_sizes, int n_in,
                              void* d_out, int out_size)
{
    const int*   wid  = (const int*)d_in[0];
    const int*   tgid = (const int*)d_in[1];
    const int*   did  = (const int*)d_in[2];
    const float* wemb = (const float*)d_in[3];
    const float* temb = (const float*)d_in[4];
    const float* demb = (const float*)d_in[5];
    const float* Wh   = (const float*)d_in[6];
    const float* bh   = (const float*)d_in[7];
    const float* Wo   = (const float*)d_in[8];
    const float* bo   = (const float*)d_in[9];
    float* out = (float*)d_out;

    dim3 grid1(N_DIM / 128, B_DIM / 128);   // (8, 128)
    gemm1_kernel<<<grid1, 256>>>(wid, tgid, did, wemb, temb, demb, Wh, bh);

    gemm2_kernel<<<B_DIM / 8, 256>>>(Wo, bo, out);
}

// round 3
// speedup vs baseline: 3.0417x; 3.0417x over previous
#include <cuda_runtime.h>
#include <cstdint>

#define B_DIM   16384
#define K_DIM   6144
#define N_DIM   1024
#define EMB     128
#define N_WORD_F 18
#define N_TAG_F  18

#define BM 128
#define BN 256
#define BK 32
#define NCHUNK (K_DIM / BK)   // 192
#define THREADS 256

// A smem: [m][k] padded stride 36 floats; B smem: [k][n] padded stride 264 floats
#define ASTRIDE 36
#define BSTRIDE 264
#define A_STAGE (BM * ASTRIDE)        // 4608 floats
#define B_STAGE (BK * BSTRIDE)        // 8448 floats
#define SMEM_FLOATS (2 * A_STAGE + 2 * B_STAGE)   // 26112 floats = 104448 B

// Scratch: hidden activations h (64 MB)
__device__ float g_h[(size_t)B_DIM * N_DIM];

__device__ __forceinline__ float tf32r(float x) {
    uint32_t u;
    asm("cvt.rna.tf32.f32 %0, %1;" : "=r"(u) : "f"(x));
    return __uint_as_float(u);
}

__device__ __forceinline__ const float* gather_row_ptr(
    int gm, int f,
    const int* __restrict__ wid, const int* __restrict__ tgid, const int* __restrict__ did,
    const float* __restrict__ wemb, const float* __restrict__ temb, const float* __restrict__ demb)
{
    if (f < N_WORD_F)                 return wemb + (size_t)wid [gm * N_WORD_F + f]              * EMB;
    else if (f < N_WORD_F + N_TAG_F)  return temb + (size_t)tgid[gm * N_TAG_F  + (f - N_WORD_F)] * EMB;
    else                              return demb + (size_t)did [gm * 12 + (f - N_WORD_F - N_TAG_F)] * EMB;
}

__device__ __forceinline__ void mma_tf32(float c[4], uint32_t a0, uint32_t a1,
                                         uint32_t a2, uint32_t a3,
                                         uint32_t b0, uint32_t b1) {
    asm volatile(
        "mma.sync.aligned.m16n8k8.row.col.f32.tf32.tf32.f32 "
        "{%0,%1,%2,%3},{%4,%5,%6,%7},{%8,%9},{%0,%1,%2,%3};"
        : "+f"(c[0]), "+f"(c[1]), "+f"(c[2]), "+f"(c[3])
        : "r"(a0), "r"(a1), "r"(a2), "r"(a3), "r"(b0), "r"(b1));
}

// ---------------------------------------------------------------------------
// GEMM1: h = relu(gather(x) @ W_h + b_h) via mma.sync tf32.
// CTA 128x256x32, 8 warps (2m x 4n), warp tile 64x64, double-buffered smem.
// ---------------------------------------------------------------------------
__global__ __launch_bounds__(THREADS, 1)
void gemm1_mma(const int* __restrict__ wid, const int* __restrict__ tgid,
               const int* __restrict__ did,
               const float* __restrict__ wemb, const float* __restrict__ temb,
               const float* __restrict__ demb,
               const float* __restrict__ Wh, const float* __restrict__ bh)
{
    extern __shared__ float smem[];
    float* Asm = smem;                 // 2 * A_STAGE
    float* Bsm = smem + 2 * A_STAGE;   // 2 * B_STAGE

    const int t    = threadIdx.x;
    const int w    = t >> 5;
    const int lane = t & 31;
    const int g    = lane >> 2;
    const int tig  = lane & 3;
    const int wm   = w & 1;            // 2 warps in M
    const int wn   = w >> 1;           // 4 warps in N
    const int m0w  = wm * 64;
    const int n0w  = wn * 64;
    const int m_blk = blockIdx.y * BM;
    const int n0    = blockIdx.x * BN;

    float acc[4][8][4];
#pragma unroll
    for (int i = 0; i < 4; ++i)
#pragma unroll
        for (int j = 0; j < 8; ++j)
#pragma unroll
            for (int q = 0; q < 4; ++q) acc[i][j][q] = 0.0f;

    // staging registers
    float4 av[4], bv[8];
    const int pm  = t >> 3;        // base m row (0..31), +32*i
    const int pkq = t & 7;         // float4 index within 32-float k slice

    auto load_chunk = [&](int c) {
        const int f  = c >> 2;
        const int kc = (c & 3) * BK;
#pragma unroll
        for (int i = 0; i < 4; ++i) {
            const float* r = gather_row_ptr(m_blk + pm + 32 * i, f, wid, tgid, did,
                                            wemb, temb, demb);
            av[i] = ((const float4*)(r + kc))[pkq];
        }
        const float* wb = Wh + (size_t)(c * BK) * N_DIM + n0;
#pragma unroll
        for (int i = 0; i < 8; ++i) {
            const int idx = t + 256 * i;
            const int kk = idx >> 6, nq = idx & 63;
            bv[i] = *(const float4*)(wb + (size_t)kk * N_DIM + 4 * nq);
        }
    };

    auto store_chunk = [&](int st) {
        float* A = Asm + st * A_STAGE;
        float* B = Bsm + st * B_STAGE;
#pragma unroll
        for (int i = 0; i < 4; ++i) {
            float4 v = av[i];
            v.x = tf32r(v.x); v.y = tf32r(v.y); v.z = tf32r(v.z); v.w = tf32r(v.w);
            *(float4*)&A[(pm + 32 * i) * ASTRIDE + 4 * pkq] = v;
        }
#pragma unroll
        for (int i = 0; i < 8; ++i) {
            const int idx = t + 256 * i;
            const int kk = idx >> 6, nq = idx & 63;
            float4 v = bv[i];
            v.x = tf32r(v.x); v.y = tf32r(v.y); v.z = tf32r(v.z); v.w = tf32r(v.w);
            *(float4*)&B[kk * BSTRIDE + 4 * nq] = v;
        }
    };

    load_chunk(0);
    store_chunk(0);
    __syncthreads();

    int buf = 0;
    for (int c = 0; c < NCHUNK; ++c) {
        if (c + 1 < NCHUNK) load_chunk(c + 1);

        const float* A = Asm + buf * A_STAGE;
        const float* B = Bsm + buf * B_STAGE;
#pragma unroll
        for (int s = 0; s < 4; ++s) {
            uint32_t a[4][4];
#pragma unroll
            for (int mt = 0; mt < 4; ++mt) {
                const int r0 = (m0w + 16 * mt + g) * ASTRIDE + 8 * s + tig;
                a[mt][0] = __float_as_uint(A[r0]);
                a[mt][1] = __float_as_uint(A[r0 + 8 * ASTRIDE]);
                a[mt][2] = __float_as_uint(A[r0 + 4]);
                a[mt][3] = __float_as_uint(A[r0 + 8 * ASTRIDE + 4]);
            }
            uint32_t b[8][2];
#pragma unroll
            for (int nt = 0; nt < 8; ++nt) {
                const int c0 = (8 * s + tig) * BSTRIDE + n0w + 8 * nt + g;
                b[nt][0] = __float_as_uint(B[c0]);
                b[nt][1] = __float_as_uint(B[c0 + 4 * BSTRIDE]);
            }
#pragma unroll
            for (int mt = 0; mt < 4; ++mt)
#pragma unroll
                for (int nt = 0; nt < 8; ++nt)
                    mma_tf32(acc[mt][nt], a[mt][0], a[mt][1], a[mt][2], a[mt][3],
                             b[nt][0], b[nt][1]);
        }

        if (c + 1 < NCHUNK) {
            store_chunk(buf ^ 1);
            __syncthreads();
            buf ^= 1;
        }
    }

    // Epilogue: + b_h, relu, store h
#pragma unroll
    for (int nt = 0; nt < 8; ++nt) {
        const int col = n0 + n0w + 8 * nt + 2 * tig;
        const float2 bb = *(const float2*)&bh[col];
#pragma unroll
        for (int mt = 0; mt < 4; ++mt) {
            const int row  = m_blk + m0w + 16 * mt + g;
            float v0 = acc[mt][nt][0] + bb.x;
            float v1 = acc[mt][nt][1] + bb.y;
            float v2 = acc[mt][nt][2] + bb.x;
            float v3 = acc[mt][nt][3] + bb.y;
            v0 = v0 > 0.f ? v0 : 0.f;  v1 = v1 > 0.f ? v1 : 0.f;
            v2 = v2 > 0.f ? v2 : 0.f;  v3 = v3 > 0.f ? v3 : 0.f;
            *(float2*)&g_h[(size_t)row * N_DIM + col]       = make_float2(v0, v1);
            *(float2*)&g_h[(size_t)(row + 8) * N_DIM + col] = make_float2(v2, v3);
        }
    }
}

// ---------------------------------------------------------------------------
// GEMM2: out = h @ W_o + b_o (N=3). One warp per row.
// ---------------------------------------------------------------------------
__global__ __launch_bounds__(256)
void gemm2_kernel(const float* __restrict__ Wo, const float* __restrict__ bo,
                  float* __restrict__ out)
{
    __shared__ float wsm[3][N_DIM];
    const int t = threadIdx.x;
    for (int i = t; i < 3 * N_DIM; i += 256) {
        int c = i / N_DIM;
        int n = i - c * N_DIM;
        wsm[c][n] = Wo[n * 3 + c];
    }
    __syncthreads();

    const int warp = t >> 5;
    const int lane = t & 31;
    const int row  = blockIdx.x * 8 + warp;

    const float* hp = g_h + (size_t)row * N_DIM;
    float s0 = 0.0f, s1 = 0.0f, s2 = 0.0f;
#pragma unroll
    for (int it = 0; it < 8; ++it) {
        const int n = it * 128 + lane * 4;
        float4 hv = *(const float4*)(hp + n);
        s0 += hv.x * wsm[0][n] + hv.y * wsm[0][n+1] + hv.z * wsm[0][n+2] + hv.w * wsm[0][n+3];
        s1 += hv.x * wsm[1][n] + hv.y * wsm[1][n+1] + hv.z * wsm[1][n+2] + hv.w * wsm[1][n+3];
        s2 += hv.x * wsm[2][n] + hv.y * wsm[2][n+1] + hv.z * wsm[2][n+2] + hv.w * wsm[2][n+3];
    }
#pragma unroll
    for (int o = 16; o; o >>= 1) {
        s0 += __shfl_xor_sync(0xffffffffu, s0, o);
        s1 += __shfl_xor_sync(0xffffffffu, s1, o);
        s2 += __shfl_xor_sync(0xffffffffu, s2, o);
    }
    if (lane == 0) {
        out[row * 3 + 0] = s0 + bo[0];
        out[row * 3 + 1] = s1 + bo[1];
        out[row * 3 + 2] = s2 + bo[2];
    }
}

extern "C" void kernel_launch(void* const* d_in, const int* in_sizes, int n_in,
                              void* d_out, int out_size)
{
    const int*   wid  = (const int*)d_in[0];
    const int*   tgid = (const int*)d_in[1];
    const int*   did  = (const int*)d_in[2];
    const float* wemb = (const float*)d_in[3];
    const float* temb = (const float*)d_in[4];
    const float* demb = (const float*)d_in[5];
    const float* Wh   = (const float*)d_in[6];
    const float* bh   = (const float*)d_in[7];
    const float* Wo   = (const float*)d_in[8];
    const float* bo   = (const float*)d_in[9];
    float* out = (float*)d_out;

    const int smem_bytes = SMEM_FLOATS * 4;   // 104448
    cudaFuncSetAttribute(gemm1_mma,
                         cudaFuncAttributeMaxDynamicSharedMemorySize, smem_bytes);

    gemm1_mma<<<dim3(N_DIM / BN, B_DIM / BM), THREADS, smem_bytes>>>(
        wid, tgid, did, wemb, temb, demb, Wh, bh);

    gemm2_kernel<<<B_DIM / 8, 256>>>(Wo, bo, out);
}

// round 4
// speedup vs baseline: 5.1207x; 1.6835x over previous
#include <cuda_runtime.h>
#include <cuda_fp16.h>
#include <cstdint>

#define B_DIM   16384
#define K_DIM   6144
#define N_DIM   1024
#define EMB     128
#define N_WORD_F 18
#define N_TAG_F  18

#define BM 128
#define BN 256
#define BK 32                  // fp32 k-elements per chunk
#define NCHUNK (K_DIM / BK)    // 192
#define THREADS 256

// A smem: half2 words Ap[m][kpair], 16 words used, stride 20 (bank-clean)
// B smem: half2 words Bp[kpair][n], 256 words used, stride 264 (bank-clean)
#define ASTR 20
#define BSTR 264
#define A_STAGE (BM * ASTR)        // 2560 words
#define B_STAGE (16 * BSTR)        // 4224 words
#define SMEM_WORDS (2 * (A_STAGE + B_STAGE))   // 13568 words = 54272 B

// Scratch: hidden activations h (64 MB)
__device__ float g_h[(size_t)B_DIM * N_DIM];

__device__ __forceinline__ uint32_t pack2(float a, float b) {
    __half2 h = __floats2half2_rn(a, b);
    return *(uint32_t*)&h;
}

__device__ __forceinline__ const float* gather_row_ptr(
    int gm, int f,
    const int* __restrict__ wid, const int* __restrict__ tgid, const int* __restrict__ did,
    const float* __restrict__ wemb, const float* __restrict__ temb, const float* __restrict__ demb)
{
    if (f < N_WORD_F)                 return wemb + (size_t)wid [gm * N_WORD_F + f]              * EMB;
    else if (f < N_WORD_F + N_TAG_F)  return temb + (size_t)tgid[gm * N_TAG_F  + (f - N_WORD_F)] * EMB;
    else                              return demb + (size_t)did [gm * 12 + (f - N_WORD_F - N_TAG_F)] * EMB;
}

__device__ __forceinline__ void mma_f16(float c[4], uint32_t a0, uint32_t a1,
                                        uint32_t a2, uint32_t a3,
                                        uint32_t b0, uint32_t b1) {
    asm volatile(
        "mma.sync.aligned.m16n8k16.row.col.f32.f16.f16.f32 "
        "{%0,%1,%2,%3},{%4,%5,%6,%7},{%8,%9},{%0,%1,%2,%3};"
        : "+f"(c[0]), "+f"(c[1]), "+f"(c[2]), "+f"(c[3])
        : "r"(a0), "r"(a1), "r"(a2), "r"(a3), "r"(b0), "r"(b1));
}

// ---------------------------------------------------------------------------
// GEMM1: h = relu(gather(x) @ W_h + b_h) via mma.sync fp16 (f32 accum).
// CTA 128x256x32, 8 warps (2m x 4n), warp tile 64x64, double-buffered smem.
// ---------------------------------------------------------------------------
__global__ __launch_bounds__(THREADS, 1)
void gemm1_mma(const int* __restrict__ wid, const int* __restrict__ tgid,
               const int* __restrict__ did,
               const float* __restrict__ wemb, const float* __restrict__ temb,
               const float* __restrict__ demb,
               const float* __restrict__ Wh, const float* __restrict__ bh)
{
    extern __shared__ uint32_t smw[];
    uint32_t* Asm = smw;                 // 2 * A_STAGE
    uint32_t* Bsm = smw + 2 * A_STAGE;   // 2 * B_STAGE

    const int t    = threadIdx.x;
    const int w    = t >> 5;
    const int lane = t & 31;
    const int g    = lane >> 2;
    const int tig  = lane & 3;
    const int wm   = w & 1;
    const int wn   = w >> 1;
    const int m0w  = wm * 64;
    const int n0w  = wn * 64;
    const int m_blk = blockIdx.y * BM;
    const int n0    = blockIdx.x * BN;

    float acc[4][8][4];
#pragma unroll
    for (int i = 0; i < 4; ++i)
#pragma unroll
        for (int j = 0; j < 8; ++j)
#pragma unroll
            for (int q = 0; q < 4; ++q) acc[i][j][q] = 0.0f;

    // A staging: thread covers rows pm+32i (i<4), float4 pkq of the 32-k slice
    const int pm  = t >> 3;
    const int pkq = t & 7;
    float4 av[4];
    // B staging: 1024 (kpair,nquad) tasks; thread t handles t+256r
    float4 bv[4][2];

    auto load_chunk = [&](int c) {
        const int f  = c >> 2;
        const int kc = (c & 3) * BK;
#pragma unroll
        for (int i = 0; i < 4; ++i) {
            const float* r = gather_row_ptr(m_blk + pm + 32 * i, f, wid, tgid, did,
                                            wemb, temb, demb);
            av[i] = ((const float4*)(r + kc))[pkq];
        }
        const float* wb = Wh + (size_t)(c * BK) * N_DIM + n0;
#pragma unroll
        for (int r = 0; r < 4; ++r) {
            const int tt = t + 256 * r;
            const int i  = tt >> 6;        // kpair 0..15
            const int nq = tt & 63;        // nquad 0..63
            bv[r][0] = *(const float4*)(wb + (size_t)(2 * i)     * N_DIM + 4 * nq);
            bv[r][1] = *(const float4*)(wb + (size_t)(2 * i + 1) * N_DIM + 4 * nq);
        }
    };

    auto store_chunk = [&](int st) {
        uint32_t* A = Asm + st * A_STAGE;
        uint32_t* B = Bsm + st * B_STAGE;
#pragma unroll
        for (int i = 0; i < 4; ++i) {
            uint2 wd = make_uint2(pack2(av[i].x, av[i].y), pack2(av[i].z, av[i].w));
            *(uint2*)&A[(pm + 32 * i) * ASTR + 2 * pkq] = wd;
        }
#pragma unroll
        for (int r = 0; r < 4; ++r) {
            const int tt = t + 256 * r;
            const int i  = tt >> 6;
            const int nq = tt & 63;
            uint4 wd = make_uint4(pack2(bv[r][0].x, bv[r][1].x),
                                  pack2(bv[r][0].y, bv[r][1].y),
                                  pack2(bv[r][0].z, bv[r][1].z),
                                  pack2(bv[r][0].w, bv[r][1].w));
            *(uint4*)&B[i * BSTR + 4 * nq] = wd;
        }
    };

    load_chunk(0);
    store_chunk(0);
    __syncthreads();

    int buf = 0;
    for (int c = 0; c < NCHUNK; ++c) {
        if (c + 1 < NCHUNK) load_chunk(c + 1);

        const uint32_t* A = Asm + buf * A_STAGE;
        const uint32_t* B = Bsm + buf * B_STAGE;
#pragma unroll
        for (int s = 0; s < 2; ++s) {
            uint32_t a[4][4];
#pragma unroll
            for (int mt = 0; mt < 4; ++mt) {
                const int row = (m0w + 16 * mt + g) * ASTR;
                a[mt][0] = A[row + 8 * s + tig];
                a[mt][1] = A[row + 8 * ASTR + 8 * s + tig];
                a[mt][2] = A[row + 8 * s + tig + 4];
                a[mt][3] = A[row + 8 * ASTR + 8 * s + tig + 4];
            }
            uint32_t b[8][2];
#pragma unroll
            for (int nt = 0; nt < 8; ++nt) {
                const int col = n0w + 8 * nt + g;
                b[nt][0] = B[(8 * s + tig)     * BSTR + col];
                b[nt][1] = B[(8 * s + tig + 4) * BSTR + col];
            }
#pragma unroll
            for (int mt = 0; mt < 4; ++mt)
#pragma unroll
                for (int nt = 0; nt < 8; ++nt)
                    mma_f16(acc[mt][nt], a[mt][0], a[mt][1], a[mt][2], a[mt][3],
                            b[nt][0], b[nt][1]);
        }

        if (c + 1 < NCHUNK) {
            store_chunk(buf ^ 1);
            __syncthreads();
            buf ^= 1;
        }
    }

    // Epilogue: + b_h, relu, store h
#pragma unroll
    for (int nt = 0; nt < 8; ++nt) {
        const int col = n0 + n0w + 8 * nt + 2 * tig;
        const float2 bb = *(const float2*)&bh[col];
#pragma unroll
        for (int mt = 0; mt < 4; ++mt) {
            const int row  = m_blk + m0w + 16 * mt + g;
            float v0 = acc[mt][nt][0] + bb.x;
            float v1 = acc[mt][nt][1] + bb.y;
            float v2 = acc[mt][nt][2] + bb.x;
            float v3 = acc[mt][nt][3] + bb.y;
            v0 = v0 > 0.f ? v0 : 0.f;  v1 = v1 > 0.f ? v1 : 0.f;
            v2 = v2 > 0.f ? v2 : 0.f;  v3 = v3 > 0.f ? v3 : 0.f;
            *(float2*)&g_h[(size_t)row * N_DIM + col]       = make_float2(v0, v1);
            *(float2*)&g_h[(size_t)(row + 8) * N_DIM + col] = make_float2(v2, v3);
        }
    }
}

// ---------------------------------------------------------------------------
// GEMM2: out = h @ W_o + b_o (N=3). One warp per row.
// ---------------------------------------------------------------------------
__global__ __launch_bounds__(256)
void gemm2_kernel(const float* __restrict__ Wo, const float* __restrict__ bo,
                  float* __restrict__ out)
{
    __shared__ float wsm[3][N_DIM];
    const int t = threadIdx.x;
    for (int i = t; i < 3 * N_DIM; i += 256) {
        int c = i / N_DIM;
        int n = i - c * N_DIM;
        wsm[c][n] = Wo[n * 3 + c];
    }
    __syncthreads();

    const int warp = t >> 5;
    const int lane = t & 31;
    const int row  = blockIdx.x * 8 + warp;

    const float* hp = g_h + (size_t)row * N_DIM;
    float s0 = 0.0f, s1 = 0.0f, s2 = 0.0f;
#pragma unroll
    for (int it = 0; it < 8; ++it) {
        const int n = it * 128 + lane * 4;
        float4 hv = *(const float4*)(hp + n);
        s0 += hv.x * wsm[0][n] + hv.y * wsm[0][n+1] + hv.z * wsm[0][n+2] + hv.w * wsm[0][n+3];
        s1 += hv.x * wsm[1][n] + hv.y * wsm[1][n+1] + hv.z * wsm[1][n+2] + hv.w * wsm[1][n+3];
        s2 += hv.x * wsm[2][n] + hv.y * wsm[2][n+1] + hv.z * wsm[2][n+2] + hv.w * wsm[2][n+3];
    }
#pragma unroll
    for (int o = 16; o; o >>= 1) {
        s0 += __shfl_xor_sync(0xffffffffu, s0, o);
        s1 += __shfl_xor_sync(0xffffffffu, s1, o);
        s2 += __shfl_xor_sync(0xffffffffu, s2, o);
    }
    if (lane == 0) {
        out[row * 3 + 0] = s0 + bo[0];
        out[row * 3 + 1] = s1 + bo[1];
        out[row * 3 + 2] = s2 + bo[2];
    }
}

extern "C" void kernel_launch(void* const* d_in, const int* in_sizes, int n_in,
                              void* d_out, int out_size)
{
    const int*   wid  = (const int*)d_in[0];
    const int*   tgid = (const int*)d_in[1];
    const int*   did  = (const int*)d_in[2];
    const float* wemb = (const float*)d_in[3];
    const float* temb = (const float*)d_in[4];
    const float* demb = (const float*)d_in[5];
    const float* Wh   = (const float*)d_in[6];
    const float* bh   = (const float*)d_in[7];
    const float* Wo   = (const float*)d_in[8];
    const float* bo   = (const float*)d_in[9];
    float* out = (float*)d_out;

    const int smem_bytes = SMEM_WORDS * 4;   // 54272
    cudaFuncSetAttribute(gemm1_mma,
                         cudaFuncAttributeMaxDynamicSharedMemorySize, smem_bytes);

    gemm1_mma<<<dim3(N_DIM / BN, B_DIM / BM), THREADS, smem_bytes>>>(
        wid, tgid, did, wemb, temb, demb, Wh, bh);

    gemm2_kernel<<<B_DIM / 8, 256>>>(Wo, bo, out);
}

// round 5
// speedup vs baseline: 6.2689x; 1.2242x over previous
#include <cuda_runtime.h>
#include <cuda_fp16.h>
#include <cstdint>

#define B_DIM   16384
#define K_DIM_W 2304          // word-only GEMM K = 18*128
#define N_DIM   1024
#define EMB     128

#define BM 128
#define BN 256
#define BK 32
#define NCHUNK (K_DIM_W / BK)   // 72
#define THREADS 256

// A smem: half2 words Ap[m][kpair], stride 20; B smem: Bp[kpair][n], stride 264
#define ASTR 20
#define BSTR 264
#define A_STAGE (BM * ASTR)          // 2560 words
#define B_STAGE (16 * BSTR)          // 4224 words
#define GEMM_WORDS (2 * (A_STAGE + B_STAGE))   // 13568 words = 54272 B

// ids region: 128 rows x 33 ints (pad) = 16896 B, round to 17024
#define IDS_STRIDE 33
#define IDS_BYTES  17024
#define SMEM_BYTES (IDS_BYTES + GEMM_WORDS * 4)   // 71296

#define TSTR 260              // T-slice smem stride (floats)

// Scratch: hidden activations (64MB) + contribution tables (5.5MB)
__device__ float g_h[(size_t)B_DIM * N_DIM];
__device__ float g_T[(size_t)1344 * N_DIM];

__device__ __forceinline__ uint32_t pack2(float a, float b) {
    __half2 h = __floats2half2_rn(a, b);
    return *(uint32_t*)&h;
}

__device__ __forceinline__ void mma_f16(float c[4], uint32_t a0, uint32_t a1,
                                        uint32_t a2, uint32_t a3,
                                        uint32_t b0, uint32_t b1) {
    asm volatile(
        "mma.sync.aligned.m16n8k16.row.col.f32.f16.f16.f32 "
        "{%0,%1,%2,%3},{%4,%5,%6,%7},{%8,%9},{%0,%1,%2,%3};"
        : "+f"(c[0]), "+f"(c[1]), "+f"(c[2]), "+f"(c[3])
        : "r"(a0), "r"(a1), "r"(a2), "r"(a3), "r"(b0), "r"(b1));
}

// ---------------------------------------------------------------------------
// Table build: T[(f,v)][n] = sum_k E[v][k] * Wh[(woff_f + k)][n]   (exact fp32)
// tag: f 0..17, base f*48, Wh rows (18+f)*128; deprel: f 18..29, base 864+(f-18)*40,
// Wh rows (36+(f-18))*128. Grid (30, 8 col-tiles), 256 threads.
// ---------------------------------------------------------------------------
__global__ void build_tables(const float* __restrict__ temb,
                             const float* __restrict__ demb,
                             const float* __restrict__ Wh)
{
    extern __shared__ float Ws[];   // [128][128]
    const int f  = blockIdx.x;
    const int ct = blockIdx.y;
    const int t  = threadIdx.x;

    const bool tag = (f < 18);
    const int nv    = tag ? 48 : 40;
    const int wrow0 = (tag ? (18 + f) : (36 + (f - 18))) * EMB;
    const int tbase = tag ? f * 48 : 864 + (f - 18) * 40;
    const float* E  = tag ? temb : demb;

#pragma unroll
    for (int i = 0; i < 64; ++i) {
        const int idx = t + 256 * i;
        const int k = idx >> 7, c = idx & 127;
        Ws[k * 128 + c] = Wh[(size_t)(wrow0 + k) * N_DIM + ct * 128 + c];
    }
    __syncthreads();

    const int c  = t & 127;
    const int v0 = t >> 7;
    for (int v = v0; v < nv; v += 2) {
        const float* e = E + (size_t)v * EMB;
        float s0 = 0.f, s1 = 0.f, s2 = 0.f, s3 = 0.f;
#pragma unroll
        for (int k = 0; k < 128; k += 4) {
            s0 = fmaf(e[k],     Ws[(k)     * 128 + c], s0);
            s1 = fmaf(e[k + 1], Ws[(k + 1) * 128 + c], s1);
            s2 = fmaf(e[k + 2], Ws[(k + 2) * 128 + c], s2);
            s3 = fmaf(e[k + 3], Ws[(k + 3) * 128 + c], s3);
        }
        g_T[(size_t)(tbase + v) * N_DIM + ct * 128 + c] = (s0 + s1) + (s2 + s3);
    }
}

// ---------------------------------------------------------------------------
// GEMM1: h = relu(x_word @ W_word + tableLookups + b_h)
// ---------------------------------------------------------------------------
__global__ __launch_bounds__(THREADS, 1)
void gemm1_mma(const int* __restrict__ wid, const int* __restrict__ tgid,
               const int* __restrict__ did,
               const float* __restrict__ wemb,
               const float* __restrict__ Wh, const float* __restrict__ bh)
{
    extern __shared__ char smem_raw[];
    int*      ids_sm = (int*)smem_raw;                         // [128][33]
    uint32_t* smw    = (uint32_t*)(smem_raw + IDS_BYTES);      // gemm bufs
    float*    T_sm   = (float*)(smem_raw + IDS_BYTES);         // reused post-mainloop
    uint32_t* Asm = smw;
    uint32_t* Bsm = smw + 2 * A_STAGE;

    const int t    = threadIdx.x;
    const int w    = t >> 5;
    const int lane = t & 31;
    const int g    = lane >> 2;
    const int tig  = lane & 3;
    const int wm   = w & 1;
    const int wn   = w >> 1;
    const int m0w  = wm * 64;
    const int n0w  = wn * 64;
    const int m_blk = blockIdx.y * BM;
    const int n0    = blockIdx.x * BN;

    // load tag/deprel ids for this CTA's rows
    for (int i = t; i < 128 * 30; i += THREADS) {
        const int row = i / 30, f = i - row * 30;
        ids_sm[row * IDS_STRIDE + f] =
            (f < 18) ? tgid[(m_blk + row) * 18 + f]
                     : did[(m_blk + row) * 12 + (f - 18)];
    }

    float acc[4][8][4];
#pragma unroll
    for (int i = 0; i < 4; ++i)
#pragma unroll
        for (int j = 0; j < 8; ++j)
#pragma unroll
            for (int q = 0; q < 4; ++q) acc[i][j][q] = 0.0f;

    const int pm  = t >> 3;
    const int pkq = t & 7;
    float4 av[4];
    float4 bv[4][2];

    auto load_chunk = [&](int c) {
        const int f  = c >> 2;
        const int kc = (c & 3) * BK;
#pragma unroll
        for (int i = 0; i < 4; ++i) {
            const int gm = m_blk + pm + 32 * i;
            const float* r = wemb + (size_t)wid[gm * 18 + f] * EMB;
            av[i] = ((const float4*)(r + kc))[pkq];
        }
        const float* wb = Wh + (size_t)(c * BK) * N_DIM + n0;
#pragma unroll
        for (int r = 0; r < 4; ++r) {
            const int tt = t + 256 * r;
            const int i  = tt >> 6;
            const int nq = tt & 63;
            bv[r][0] = *(const float4*)(wb + (size_t)(2 * i)     * N_DIM + 4 * nq);
            bv[r][1] = *(const float4*)(wb + (size_t)(2 * i + 1) * N_DIM + 4 * nq);
        }
    };

    auto store_chunk = [&](int st) {
        uint32_t* A = Asm + st * A_STAGE;
        uint32_t* B = Bsm + st * B_STAGE;
#pragma unroll
        for (int i = 0; i < 4; ++i) {
            uint2 wd = make_uint2(pack2(av[i].x, av[i].y), pack2(av[i].z, av[i].w));
            *(uint2*)&A[(pm + 32 * i) * ASTR + 2 * pkq] = wd;
        }
#pragma unroll
        for (int r = 0; r < 4; ++r) {
            const int tt = t + 256 * r;
            const int i  = tt >> 6;
            const int nq = tt & 63;
            uint4 wd = make_uint4(pack2(bv[r][0].x, bv[r][1].x),
                                  pack2(bv[r][0].y, bv[r][1].y),
                                  pack2(bv[r][0].z, bv[r][1].z),
                                  pack2(bv[r][0].w, bv[r][1].w));
            *(uint4*)&B[i * BSTR + 4 * nq] = wd;
        }
    };

    load_chunk(0);
    store_chunk(0);
    __syncthreads();

    int buf = 0;
    for (int c = 0; c < NCHUNK; ++c) {
        if (c + 1 < NCHUNK) load_chunk(c + 1);

        const uint32_t* A = Asm + buf * A_STAGE;
        const uint32_t* B = Bsm + buf * B_STAGE;
#pragma unroll
        for (int s = 0; s < 2; ++s) {
            uint32_t a[4][4];
#pragma unroll
            for (int mt = 0; mt < 4; ++mt) {
                const int row = (m0w + 16 * mt + g) * ASTR;
                a[mt][0] = A[row + 8 * s + tig];
                a[mt][1] = A[row + 8 * ASTR + 8 * s + tig];
                a[mt][2] = A[row + 8 * s + tig + 4];
                a[mt][3] = A[row + 8 * ASTR + 8 * s + tig + 4];
            }
            uint32_t b[8][2];
#pragma unroll
            for (int nt = 0; nt < 8; ++nt) {
                const int col = n0w + 8 * nt + g;
                b[nt][0] = B[(8 * s + tig)     * BSTR + col];
                b[nt][1] = B[(8 * s + tig + 4) * BSTR + col];
            }
#pragma unroll
            for (int mt = 0; mt < 4; ++mt)
#pragma unroll
                for (int nt = 0; nt < 8; ++nt)
                    mma_f16(acc[mt][nt], a[mt][0], a[mt][1], a[mt][2], a[mt][3],
                            b[nt][0], b[nt][1]);
        }

        if (c + 1 < NCHUNK) {
            store_chunk(buf ^ 1);
            __syncthreads();
            buf ^= 1;
        }
    }

    // ---- table-lookup accumulation: 30 features ----
    for (int f = 0; f < 30; ++f) {
        const bool tag = (f < 18);
        const int nv    = tag ? 48 : 40;
        const int tbase = tag ? f * 48 : 864 + (f - 18) * 40;

        __syncthreads();   // protect T_sm overwrite
        const int tot = nv * 64;   // float4 count
        for (int i = t; i < tot; i += THREADS) {
            const int v = i >> 6, cq = i & 63;
            float4 val = *(const float4*)&g_T[(size_t)(tbase + v) * N_DIM + n0 + 4 * cq];
            *(float4*)&T_sm[v * TSTR + 4 * cq] = val;
        }
        __syncthreads();

#pragma unroll
        for (int mt = 0; mt < 4; ++mt) {
            const int r0 = m0w + 16 * mt + g;
            const int id0 = ids_sm[r0 * IDS_STRIDE + f];
            const int id1 = ids_sm[(r0 + 8) * IDS_STRIDE + f];
            const float* t0 = &T_sm[id0 * TSTR + n0w];
            const float* t1 = &T_sm[id1 * TSTR + n0w];
#pragma unroll
            for (int nt = 0; nt < 8; ++nt) {
                const float2 v0 = *(const float2*)&t0[8 * nt + 2 * tig];
                const float2 v1 = *(const float2*)&t1[8 * nt + 2 * tig];
                acc[mt][nt][0] += v0.x;  acc[mt][nt][1] += v0.y;
                acc[mt][nt][2] += v1.x;  acc[mt][nt][3] += v1.y;
            }
        }
    }

    // Epilogue: + b_h, relu, store h
#pragma unroll
    for (int nt = 0; nt < 8; ++nt) {
        const int col = n0 + n0w + 8 * nt + 2 * tig;
        const float2 bb = *(const float2*)&bh[col];
#pragma unroll
        for (int mt = 0; mt < 4; ++mt) {
            const int row = m_blk + m0w + 16 * mt + g;
            float v0 = acc[mt][nt][0] + bb.x;
            float v1 = acc[mt][nt][1] + bb.y;
            float v2 = acc[mt][nt][2] + bb.x;
            float v3 = acc[mt][nt][3] + bb.y;
            v0 = v0 > 0.f ? v0 : 0.f;  v1 = v1 > 0.f ? v1 : 0.f;
            v2 = v2 > 0.f ? v2 : 0.f;  v3 = v3 > 0.f ? v3 : 0.f;
            *(float2*)&g_h[(size_t)row * N_DIM + col]       = make_float2(v0, v1);
            *(float2*)&g_h[(size_t)(row + 8) * N_DIM + col] = make_float2(v2, v3);
        }
    }
}

// ---------------------------------------------------------------------------
// GEMM2: out = h @ W_o + b_o (N=3). One warp per row.
// ---------------------------------------------------------------------------
__global__ __launch_bounds__(256)
void gemm2_kernel(const float* __restrict__ Wo, const float* __restrict__ bo,
                  float* __restrict__ out)
{
    __shared__ float wsm[3][N_DIM];
    const int t = threadIdx.x;
    for (int i = t; i < 3 * N_DIM; i += 256) {
        int c = i / N_DIM;
        int n = i - c * N_DIM;
        wsm[c][n] = Wo[n * 3 + c];
    }
    __syncthreads();

    const int warp = t >> 5;
    const int lane = t & 31;
    const int row  = blockIdx.x * 8 + warp;

    const float* hp = g_h + (size_t)row * N_DIM;
    float s0 = 0.0f, s1 = 0.0f, s2 = 0.0f;
#pragma unroll
    for (int it = 0; it < 8; ++it) {
        const int n = it * 128 + lane * 4;
        float4 hv = *(const float4*)(hp + n);
        s0 += hv.x * wsm[0][n] + hv.y * wsm[0][n+1] + hv.z * wsm[0][n+2] + hv.w * wsm[0][n+3];
        s1 += hv.x * wsm[1][n] + hv.y * wsm[1][n+1] + hv.z * wsm[1][n+2] + hv.w * wsm[1][n+3];
        s2 += hv.x * wsm[2][n] + hv.y * wsm[2][n+1] + hv.z * wsm[2][n+2] + hv.w * wsm[2][n+3];
    }
#pragma unroll
    for (int o = 16; o; o >>= 1) {
        s0 += __shfl_xor_sync(0xffffffffu, s0, o);
        s1 += __shfl_xor_sync(0xffffffffu, s1, o);
        s2 += __shfl_xor_sync(0xffffffffu, s2, o);
    }
    if (lane == 0) {
        out[row * 3 + 0] = s0 + bo[0];
        out[row * 3 + 1] = s1 + bo[1];
        out[row * 3 + 2] = s2 + bo[2];
    }
}

extern "C" void kernel_launch(void* const* d_in, const int* in_sizes, int n_in,
                              void* d_out, int out_size)
{
    const int*   wid  = (const int*)d_in[0];
    const int*   tgid = (const int*)d_in[1];
    const int*   did  = (const int*)d_in[2];
    const float* wemb = (const float*)d_in[3];
    const float* temb = (const float*)d_in[4];
    const float* demb = (const float*)d_in[5];
    const float* Wh   = (const float*)d_in[6];
    const float* bh   = (const float*)d_in[7];
    const float* Wo   = (const float*)d_in[8];
    const float* bo   = (const float*)d_in[9];
    float* out = (float*)d_out;

    cudaFuncSetAttribute(build_tables,
                         cudaFuncAttributeMaxDynamicSharedMemorySize, 128 * 128 * 4);
    cudaFuncSetAttribute(gemm1_mma,
                         cudaFuncAttributeMaxDynamicSharedMemorySize, SMEM_BYTES);

    build_tables<<<dim3(30, 8), 256, 128 * 128 * 4>>>(temb, demb, Wh);

    gemm1_mma<<<dim3(N_DIM / BN, B_DIM / BM), THREADS, SMEM_BYTES>>>(
        wid, tgid, did, wemb, Wh, bh);

    gemm2_kernel<<<B_DIM / 8, 256>>>(Wo, bo, out);
}

// round 6
// speedup vs baseline: 7.4223x; 1.1840x over previous
#include <cuda_runtime.h>
#include <cuda_fp16.h>
#include <cstdint>

#define B_DIM   16384
#define N_DIM   1024
#define EMB     128
#define N_WORD  100000

#define BM 128
#define BN 256
#define NCHUNK 72            // 72 chunks of 32 k (word slice K=2304)
#define THREADS 256

#define ASTR 20              // A smem row stride (uint32 words)
#define BSTR 264             // B smem row stride (uint32 words)
#define A_STAGE (BM * ASTR)        // 2560 words
#define B_STAGE (16 * BSTR)        // 4224 words

#define IDS_BYTES   24576                  // 128 rows x 48 ids
#define TWORDS      (48 * 260)             // one table buffer: 12480 floats
#define UNION_BYTES (2 * TWORDS * 4)       // 99840 (gemm bufs 54272 fit inside)
#define WO_BYTES    3072
#define SMEM_BYTES  (IDS_BYTES + UNION_BYTES + WO_BYTES)   // 127488

// ---- device scratch ----
__device__ uint32_t g_Ap[(size_t)N_WORD * 64];     // word emb, half2 k-pairs (25.6MB)
__device__ uint32_t g_Bp[(size_t)1152 * N_DIM];    // word W_h slice, half2 k-pairs (4.7MB)
__device__ float    g_T[(size_t)1344 * N_DIM];     // tag/deprel contribution tables (5.5MB)
__device__ float    g_part[(size_t)16 * B_DIM * 3];// partial out dots (3.1MB)

// ---- helpers ----
__device__ __forceinline__ uint32_t smem_u32(const void* p) {
    uint32_t a;
    asm("{ .reg .u64 t; cvta.to.shared.u64 t, %1; cvt.u32.u64 %0, t; }" : "=r"(a) : "l"(p));
    return a;
}
__device__ __forceinline__ void cp16(uint32_t dst, const void* src) {
    asm volatile("cp.async.cg.shared.global [%0], [%1], 16;" :: "r"(dst), "l"(src) : "memory");
}
#define CP_COMMIT() asm volatile("cp.async.commit_group;" ::: "memory")
#define CP_WAIT(n)  asm volatile("cp.async.wait_group %0;" :: "n"(n) : "memory")

__device__ __forceinline__ uint32_t pack2(float a, float b) {
    __half2 h = __floats2half2_rn(a, b);
    return *(uint32_t*)&h;
}
__device__ __forceinline__ void mma_f16(float c[4], uint32_t a0, uint32_t a1,
                                        uint32_t a2, uint32_t a3,
                                        uint32_t b0, uint32_t b1) {
    asm volatile(
        "mma.sync.aligned.m16n8k16.row.col.f32.f16.f16.f32 "
        "{%0,%1,%2,%3},{%4,%5,%6,%7},{%8,%9},{%0,%1,%2,%3};"
        : "+f"(c[0]), "+f"(c[1]), "+f"(c[2]), "+f"(c[3])
        : "r"(a0), "r"(a1), "r"(a2), "r"(a3), "r"(b0), "r"(b1));
}

// ---------------------------------------------------------------------------
// Prep: pack word embeddings to half2 k-pairs
// ---------------------------------------------------------------------------
__global__ void pack_e16(const float* __restrict__ wemb)
{
    const size_t i = (size_t)blockIdx.x * 256 + threadIdx.x;   // word index (id*64+w)
    if (i >= (size_t)N_WORD * 64) return;
    const float2 v = *(const float2*)(wemb + 2 * i);
    g_Ap[i] = pack2(v.x, v.y);
}

// Prep: pack word-slice of W_h (rows 0..2303) into k-pair-major half2
__global__ void pack_whp(const float* __restrict__ Wh)
{
    const int i = blockIdx.x * 256 + threadIdx.x;   // kp*1024 + n
    const int kp = i >> 10, n = i & 1023;
    g_Bp[i] = pack2(Wh[(size_t)(2 * kp) * N_DIM + n],
                    Wh[(size_t)(2 * kp + 1) * N_DIM + n]);
}

// ---------------------------------------------------------------------------
// Prep: T[(f,v)][n] = sum_k E[v][k] * Wh[wrow0_f + k][n]  (exact fp32)
// grid (30, 8, 3): feature, 128-col tile, 16-value v-tile. 256 threads.
// ---------------------------------------------------------------------------
__global__ void build_tables(const float* __restrict__ temb,
                             const float* __restrict__ demb,
                             const float* __restrict__ Wh)
{
    extern __shared__ float bs[];
    float* Ws = bs;            // [128][128]
    float* es = bs + 16384;    // [16][128]

    const int f = blockIdx.x, ct = blockIdx.y, z = blockIdx.z;
    const int t = threadIdx.x;
    const bool tag = (f < 18);
    const int nv    = tag ? 48 : 40;
    const int wrow0 = (tag ? (18 + f) : (36 + (f - 18))) * EMB;
    const int tbase = tag ? f * 48 : 864 + (f - 18) * 40;
    const float* E  = tag ? temb : demb;

    for (int i = t; i < 16384; i += 256) {
        const int k = i >> 7, c = i & 127;
        Ws[i] = Wh[(size_t)(wrow0 + k) * N_DIM + ct * 128 + c];
    }
    for (int i = t; i < 2048; i += 256) {
        const int v = z * 16 + (i >> 7), c = i & 127;
        es[i] = (v < nv) ? E[v * EMB + c] : 0.0f;
    }
    __syncthreads();

    const int c  = t & 127;
    const int vl = t >> 7;
    float s[8];
#pragma unroll
    for (int j = 0; j < 8; ++j) s[j] = 0.0f;

    for (int k = 0; k < 128; ++k) {
        const float wv = Ws[k * 128 + c];
#pragma unroll
        for (int j = 0; j < 8; ++j)
            s[j] = fmaf(es[(vl + 2 * j) * 128 + k], wv, s[j]);
    }
#pragma unroll
    for (int j = 0; j < 8; ++j) {
        const int v = z * 16 + vl + 2 * j;
        if (v < nv) g_T[(size_t)(tbase + v) * N_DIM + ct * 128 + c] = s[j];
    }
}

// ---------------------------------------------------------------------------
// GEMM1: fused  partial_out = relu(x_word@W_word + tables + b_h) @ W_o-slice
// ---------------------------------------------------------------------------
__global__ __launch_bounds__(THREADS, 1)
void gemm1_mma(const int* __restrict__ wid, const int* __restrict__ tgid,
               const int* __restrict__ did,
               const float* __restrict__ bh, const float* __restrict__ Wo)
{
    extern __shared__ char sm[];
    int*      ids  = (int*)sm;                              // [128][48]
    uint32_t* gw   = (uint32_t*)(sm + IDS_BYTES);           // gemm bufs (union)
    float*    Tun  = (float*)(sm + IDS_BYTES);              // table bufs (union)
    float*    wo   = (float*)(sm + IDS_BYTES + UNION_BYTES);

    const int t    = threadIdx.x;
    const int w    = t >> 5;
    const int lane = t & 31;
    const int g    = lane >> 2;
    const int tig  = lane & 3;
    const int wm   = w & 1;
    const int wn   = w >> 1;
    const int m0w  = wm * 64;
    const int n0w  = wn * 64;
    const int m_blk = blockIdx.y * BM;
    const int n0    = blockIdx.x * BN;

    const uint32_t sbase  = smem_u32(sm);
    const uint32_t a_u32  = sbase + IDS_BYTES;
    const uint32_t b_u32  = a_u32 + 2 * A_STAGE * 4;
    const uint32_t t_u32  = sbase + IDS_BYTES;

    // ---- stage ids (word 0..17, tag 18..35, deprel 36..47) ----
    for (int i = t; i < 128 * 48; i += THREADS) {
        const int row = i / 48, f = i - row * 48;
        int v;
        if (f < 18)      v = wid [(m_blk + row) * 18 + f];
        else if (f < 36) v = tgid[(m_blk + row) * 18 + (f - 18)];
        else             v = did [(m_blk + row) * 12 + (f - 36)];
        ids[row * 48 + f] = v;
    }
    // ---- stage W_o slice ----
    for (int i = t; i < 768; i += THREADS)
        wo[i] = Wo[(size_t)n0 * 3 + i];
    __syncthreads();

    float acc[4][8][4];
#pragma unroll
    for (int i = 0; i < 4; ++i)
#pragma unroll
        for (int j = 0; j < 8; ++j)
#pragma unroll
            for (int q = 0; q < 4; ++q) acc[i][j][q] = 0.0f;

    // ---- async producers ----
    auto issueA = [&](int c, int st) {
        const int f   = c >> 2;
        const int kpo = (c & 3) * 16;
        const uint32_t db = a_u32 + st * A_STAGE * 4;
#pragma unroll
        for (int r = 0; r < 2; ++r) {
            const int idx = t + 256 * r;
            const int row = idx >> 2, q = idx & 3;
            const int id  = ids[row * 48 + f];
            cp16(db + (row * ASTR + 4 * q) * 4,
                 g_Ap + (size_t)id * 64 + kpo + 4 * q);
        }
    };
    auto issueB = [&](int c, int st) {
        const uint32_t db = b_u32 + st * B_STAGE * 4;
        const uint32_t* src = g_Bp + (size_t)(c * 16) * N_DIM + n0;
#pragma unroll
        for (int r = 0; r < 4; ++r) {
            const int idx = t + 256 * r;
            const int kp = idx >> 6, q = idx & 63;
            cp16(db + (kp * BSTR + 4 * q) * 4, src + (size_t)kp * N_DIM + 4 * q);
        }
    };

    issueA(0, 0); issueB(0, 0); CP_COMMIT();

    int buf = 0;
    for (int c = 0; c < NCHUNK; ++c) {
        if (c + 1 < NCHUNK) {
            issueA(c + 1, buf ^ 1); issueB(c + 1, buf ^ 1); CP_COMMIT();
            CP_WAIT(1);
        } else {
            CP_WAIT(0);
        }
        __syncthreads();

        const uint32_t* A = gw + buf * A_STAGE;
        const uint32_t* B = gw + 2 * A_STAGE + buf * B_STAGE;
#pragma unroll
        for (int s = 0; s < 2; ++s) {
            uint32_t a[4][4];
#pragma unroll
            for (int mt = 0; mt < 4; ++mt) {
                const int row = (m0w + 16 * mt + g) * ASTR;
                a[mt][0] = A[row + 8 * s + tig];
                a[mt][1] = A[row + 8 * ASTR + 8 * s + tig];
                a[mt][2] = A[row + 8 * s + tig + 4];
                a[mt][3] = A[row + 8 * ASTR + 8 * s + tig + 4];
            }
            uint32_t b[8][2];
#pragma unroll
            for (int nt = 0; nt < 8; ++nt) {
                const int col = n0w + 8 * nt + g;
                b[nt][0] = B[(8 * s + tig)     * BSTR + col];
                b[nt][1] = B[(8 * s + tig + 4) * BSTR + col];
            }
#pragma unroll
            for (int mt = 0; mt < 4; ++mt)
#pragma unroll
                for (int nt = 0; nt < 8; ++nt)
                    mma_f16(acc[mt][nt], a[mt][0], a[mt][1], a[mt][2], a[mt][3],
                            b[nt][0], b[nt][1]);
        }
        __syncthreads();
        buf ^= 1;
    }

    // ---- table accumulation (30 features, double-buffered cp.async) ----
    auto issueT = [&](int f, int st) {
        const bool tag = (f < 18);
        const int nv    = tag ? 48 : 40;
        const int tbase = tag ? f * 48 : 864 + (f - 18) * 40;
        const int tot   = nv * 64;
        const uint32_t db = t_u32 + st * TWORDS * 4;
        for (int i = t; i < tot; i += THREADS) {
            const int v = i >> 6, q = i & 63;
            cp16(db + (v * 260 + 4 * q) * 4,
                 g_T + (size_t)(tbase + v) * N_DIM + n0 + 4 * q);
        }
    };

    issueT(0, 0); CP_COMMIT();
    int tb = 0;
    for (int f = 0; f < 30; ++f) {
        if (f + 1 < 30) { issueT(f + 1, tb ^ 1); CP_COMMIT(); CP_WAIT(1); }
        else            { CP_WAIT(0); }
        __syncthreads();

        const float* T = Tun + tb * TWORDS;
        const int fc = 18 + f;       // ids column
#pragma unroll
        for (int mt = 0; mt < 4; ++mt) {
            const int r0  = m0w + 16 * mt + g;
            const int id0 = ids[r0 * 48 + fc];
            const int id1 = ids[(r0 + 8) * 48 + fc];
            const float* t0 = T + id0 * 260 + n0w;
            const float* t1 = T + id1 * 260 + n0w;
#pragma unroll
            for (int nt = 0; nt < 8; ++nt) {
                const float2 v0 = *(const float2*)&t0[8 * nt + 2 * tig];
                const float2 v1 = *(const float2*)&t1[8 * nt + 2 * tig];
                acc[mt][nt][0] += v0.x;  acc[mt][nt][1] += v0.y;
                acc[mt][nt][2] += v1.x;  acc[mt][nt][3] += v1.y;
            }
        }
        __syncthreads();
        tb ^= 1;
    }

    // ---- epilogue: bias + relu + partial dot with W_o slice ----
    float p[4][2][3];
#pragma unroll
    for (int mt = 0; mt < 4; ++mt)
#pragma unroll
        for (int h = 0; h < 2; ++h)
#pragma unroll
            for (int cc = 0; cc < 3; ++cc) p[mt][h][cc] = 0.0f;

#pragma unroll
    for (int nt = 0; nt < 8; ++nt) {
        const int colq = n0w + 8 * nt + 2 * tig;
        const float w00 = wo[colq * 3 + 0], w01 = wo[colq * 3 + 1], w02 = wo[colq * 3 + 2];
        const float w10 = wo[colq * 3 + 3], w11 = wo[colq * 3 + 4], w12 = wo[colq * 3 + 5];
        const float2 bb = *(const float2*)&bh[n0 + colq];
#pragma unroll
        for (int mt = 0; mt < 4; ++mt) {
            float v0 = acc[mt][nt][0] + bb.x;
            float v1 = acc[mt][nt][1] + bb.y;
            float v2 = acc[mt][nt][2] + bb.x;
            float v3 = acc[mt][nt][3] + bb.y;
            v0 = v0 > 0.f ? v0 : 0.f;  v1 = v1 > 0.f ? v1 : 0.f;
            v2 = v2 > 0.f ? v2 : 0.f;  v3 = v3 > 0.f ? v3 : 0.f;
            p[mt][0][0] += v0 * w00 + v1 * w10;
            p[mt][0][1] += v0 * w01 + v1 * w11;
            p[mt][0][2] += v0 * w02 + v1 * w12;
            p[mt][1][0] += v2 * w00 + v3 * w10;
            p[mt][1][1] += v2 * w01 + v3 * w11;
            p[mt][1][2] += v2 * w02 + v3 * w12;
        }
    }
    // reduce over tig (lanes g*4+tig): xor 1, 2
#pragma unroll
    for (int mt = 0; mt < 4; ++mt)
#pragma unroll
        for (int h = 0; h < 2; ++h)
#pragma unroll
            for (int cc = 0; cc < 3; ++cc) {
                float x = p[mt][h][cc];
                x += __shfl_xor_sync(0xffffffffu, x, 1);
                x += __shfl_xor_sync(0xffffffffu, x, 2);
                p[mt][h][cc] = x;
            }
    if (tig == 0) {
        const int slot = blockIdx.x * 4 + wn;
#pragma unroll
        for (int mt = 0; mt < 4; ++mt)
#pragma unroll
            for (int h = 0; h < 2; ++h) {
                const int row = m_blk + m0w + 16 * mt + g + 8 * h;
                float* dst = g_part + ((size_t)slot * B_DIM + row) * 3;
                dst[0] = p[mt][h][0];
                dst[1] = p[mt][h][1];
                dst[2] = p[mt][h][2];
            }
    }
}

// ---------------------------------------------------------------------------
// Final reduce: out[row] = sum_slots g_part + b_o
// ---------------------------------------------------------------------------
__global__ __launch_bounds__(256)
void reduce_out(const float* __restrict__ bo, float* __restrict__ out)
{
    const int row = blockIdx.x * 256 + threadIdx.x;
    float s0 = bo[0], s1 = bo[1], s2 = bo[2];
#pragma unroll
    for (int sl = 0; sl < 16; ++sl) {
        const float* p = g_part + ((size_t)sl * B_DIM + row) * 3;
        s0 += p[0]; s1 += p[1]; s2 += p[2];
    }
    out[row * 3 + 0] = s0;
    out[row * 3 + 1] = s1;
    out[row * 3 + 2] = s2;
}

extern "C" void kernel_launch(void* const* d_in, const int* in_sizes, int n_in,
                              void* d_out, int out_size)
{
    const int*   wid  = (const int*)d_in[0];
    const int*   tgid = (const int*)d_in[1];
    const int*   did  = (const int*)d_in[2];
    const float* wemb = (const float*)d_in[3];
    const float* temb = (const float*)d_in[4];
    const float* demb = (const float*)d_in[5];
    const float* Wh   = (const float*)d_in[6];
    const float* bh   = (const float*)d_in[7];
    const float* Wo   = (const float*)d_in[8];
    const float* bo   = (const float*)d_in[9];
    float* out = (float*)d_out;

    cudaFuncSetAttribute(build_tables,
                         cudaFuncAttributeMaxDynamicSharedMemorySize, 73728);
    cudaFuncSetAttribute(gemm1_mma,
                         cudaFuncAttributeMaxDynamicSharedMemorySize, SMEM_BYTES);

    pack_e16<<<(N_WORD * 64 + 255) / 256, 256>>>(wemb);
    pack_whp<<<1152 * N_DIM / 256, 256>>>(Wh);
    build_tables<<<dim3(30, 8, 3), 256, 73728>>>(temb, demb, Wh);

    gemm1_mma<<<dim3(N_DIM / BN, B_DIM / BM), THREADS, SMEM_BYTES>>>(
        wid, tgid, did, bh, Wo);

    reduce_out<<<B_DIM / 256, 256>>>(bo, out);
}

// round 7
// speedup vs baseline: 8.5910x; 1.1575x over previous
#include <cuda_runtime.h>
#include <cuda_fp16.h>
#include <cstdint>

#define B_DIM   16384
#define N_DIM   1024
#define EMB     128
#define N_WORD  100000

#define BM 128
#define BN 128
#define NCHUNK 72            // word slice K = 2304 = 72 x 32
#define THREADS 256
#define NSTAGE 3

#define ASTR 20              // A smem row stride (uint32 words)
#define BSTR 136             // B smem row stride (uint32 words)
#define A_STAGE (BM * ASTR)        // 2560 words
#define B_STAGE (16 * BSTR)        // 2176 words
#define STAGE_WORDS (A_STAGE + B_STAGE)          // 4736
#define GEMM_BYTES  (NSTAGE * STAGE_WORDS * 4)   // 56832

#define IDS_BYTES   24576                  // 128 rows x 48 ids
#define TSTR  132
#define TWORDS (48 * TSTR)                 // 6336 floats per table buffer
#define UNION_BYTES 56832                  // gemm bufs (2 table bufs = 50688 fit)
#define WO_BYTES    2048
#define SMEM_BYTES  (IDS_BYTES + UNION_BYTES + WO_BYTES)   // 83456

// ---- device scratch ----
__device__ uint32_t g_Ap[(size_t)N_WORD * 64];      // word emb, half2 k-pairs
__device__ uint32_t g_Bp[(size_t)1152 * N_DIM];     // word W_h slice, half2 k-pairs
__device__ float    g_T[(size_t)1344 * N_DIM];      // tag/deprel tables (fp32)
__device__ float    g_part[(size_t)32 * B_DIM * 3]; // partial out dots

// ---- helpers ----
__device__ __forceinline__ uint32_t smem_u32(const void* p) {
    uint32_t a;
    asm("{ .reg .u64 t; cvta.to.shared.u64 t, %1; cvt.u32.u64 %0, t; }" : "=r"(a) : "l"(p));
    return a;
}
__device__ __forceinline__ void cp16(uint32_t dst, const void* src) {
    asm volatile("cp.async.cg.shared.global [%0], [%1], 16;" :: "r"(dst), "l"(src) : "memory");
}
#define CP_COMMIT() asm volatile("cp.async.commit_group;" ::: "memory")
#define CP_WAIT(n)  asm volatile("cp.async.wait_group %0;" :: "n"(n) : "memory")

__device__ __forceinline__ uint32_t pack2(float a, float b) {
    __half2 h = __floats2half2_rn(a, b);
    return *(uint32_t*)&h;
}
__device__ __forceinline__ void mma_f16(float c[4], uint32_t a0, uint32_t a1,
                                        uint32_t a2, uint32_t a3,
                                        uint32_t b0, uint32_t b1) {
    asm volatile(
        "mma.sync.aligned.m16n8k16.row.col.f32.f16.f16.f32 "
        "{%0,%1,%2,%3},{%4,%5,%6,%7},{%8,%9},{%0,%1,%2,%3};"
        : "+f"(c[0]), "+f"(c[1]), "+f"(c[2]), "+f"(c[3])
        : "r"(a0), "r"(a1), "r"(a2), "r"(a3), "r"(b0), "r"(b1));
}

// ---------------------------------------------------------------------------
// Prep kernels
// ---------------------------------------------------------------------------
__global__ void pack_e16(const float* __restrict__ wemb)
{
    const size_t i = (size_t)blockIdx.x * 256 + threadIdx.x;   // float4 index
    if (i >= (size_t)N_WORD * 32) return;
    const float4 v = ((const float4*)wemb)[i];
    *(uint2*)&g_Ap[2 * i] = make_uint2(pack2(v.x, v.y), pack2(v.z, v.w));
}

__global__ void pack_whp(const float* __restrict__ Wh)
{
    const int i = blockIdx.x * 256 + threadIdx.x;   // kp*1024 + n
    const int kp = i >> 10, n = i & 1023;
    g_Bp[i] = pack2(Wh[(size_t)(2 * kp) * N_DIM + n],
                    Wh[(size_t)(2 * kp + 1) * N_DIM + n]);
}

// T[(f,v)][n] = sum_k E[v][k] * Wh[wrow0_f + k][n]  (exact fp32)
__global__ void build_tables(const float* __restrict__ temb,
                             const float* __restrict__ demb,
                             const float* __restrict__ Wh)
{
    extern __shared__ float bs[];
    float* Ws = bs;            // [128][128]
    float* es = bs + 16384;    // [16][128]

    const int f = blockIdx.x, ct = blockIdx.y, z = blockIdx.z;
    const int t = threadIdx.x;
    const bool tag = (f < 18);
    const int nv    = tag ? 48 : 40;
    const int wrow0 = (tag ? (18 + f) : (36 + (f - 18))) * EMB;
    const int tbase = tag ? f * 48 : 864 + (f - 18) * 40;
    const float* E  = tag ? temb : demb;

    for (int i = t; i < 16384; i += 256) {
        const int k = i >> 7, c = i & 127;
        Ws[i] = Wh[(size_t)(wrow0 + k) * N_DIM + ct * 128 + c];
    }
    for (int i = t; i < 2048; i += 256) {
        const int v = z * 16 + (i >> 7), c = i & 127;
        es[i] = (v < nv) ? E[v * EMB + c] : 0.0f;
    }
    __syncthreads();

    const int c  = t & 127;
    const int vl = t >> 7;
    float s[8];
#pragma unroll
    for (int j = 0; j < 8; ++j) s[j] = 0.0f;
    for (int k = 0; k < 128; ++k) {
        const float wv = Ws[k * 128 + c];
#pragma unroll
        for (int j = 0; j < 8; ++j)
            s[j] = fmaf(es[(vl + 2 * j) * 128 + k], wv, s[j]);
    }
#pragma unroll
    for (int j = 0; j < 8; ++j) {
        const int v = z * 16 + vl + 2 * j;
        if (v < nv) g_T[(size_t)(tbase + v) * N_DIM + ct * 128 + c] = s[j];
    }
}

// ---------------------------------------------------------------------------
// Fused GEMM1 + epilogue dot
// ---------------------------------------------------------------------------
__global__ __launch_bounds__(THREADS, 2)
void gemm1_mma(const int* __restrict__ wid, const int* __restrict__ tgid,
               const int* __restrict__ did,
               const float* __restrict__ bh, const float* __restrict__ Wo)
{
    extern __shared__ char sm[];
    int*      ids  = (int*)sm;                              // [128][48]
    uint32_t* gw   = (uint32_t*)(sm + IDS_BYTES);           // gemm bufs (union)
    float*    Tun  = (float*)(sm + IDS_BYTES);              // table bufs (union)
    float*    wo   = (float*)(sm + IDS_BYTES + UNION_BYTES);

    const int t    = threadIdx.x;
    const int w    = t >> 5;
    const int lane = t & 31;
    const int g    = lane >> 2;
    const int tig  = lane & 3;
    const int wm   = w & 1;
    const int wn   = w >> 1;
    const int m0w  = wm * 64;
    const int n0w  = wn * 32;
    const int m_blk = blockIdx.y * BM;
    const int n0    = blockIdx.x * BN;

    const uint32_t sbase  = smem_u32(sm);
    const uint32_t gw_u32 = sbase + IDS_BYTES;
    const uint32_t t_u32  = sbase + IDS_BYTES;

    for (int i = t; i < 128 * 48; i += THREADS) {
        const int row = i / 48, f = i - row * 48;
        int v;
        if (f < 18)      v = wid [(m_blk + row) * 18 + f];
        else if (f < 36) v = tgid[(m_blk + row) * 18 + (f - 18)];
        else             v = did [(m_blk + row) * 12 + (f - 36)];
        ids[row * 48 + f] = v;
    }
    for (int i = t; i < 384; i += THREADS)
        wo[i] = Wo[(size_t)n0 * 3 + i];
    __syncthreads();

    float acc[4][4][4];
#pragma unroll
    for (int i = 0; i < 4; ++i)
#pragma unroll
        for (int j = 0; j < 4; ++j)
#pragma unroll
            for (int q = 0; q < 4; ++q) acc[i][j][q] = 0.0f;

    auto issue = [&](int c, int st) {
        const int f   = c >> 2;
        const int kpo = (c & 3) * 16;
        const uint32_t ab = gw_u32 + st * STAGE_WORDS * 4;
        const uint32_t bb = ab + A_STAGE * 4;
#pragma unroll
        for (int r = 0; r < 2; ++r) {        // A: 512 cp16
            const int idx = t + 256 * r;
            const int row = idx >> 2, q = idx & 3;
            const int id  = ids[row * 48 + f];
            cp16(ab + (row * ASTR + 4 * q) * 4,
                 g_Ap + (size_t)id * 64 + kpo + 4 * q);
        }
        const uint32_t* src = g_Bp + (size_t)(c * 16) * N_DIM + n0;
#pragma unroll
        for (int r = 0; r < 2; ++r) {        // B: 512 cp16
            const int idx = t + 256 * r;
            const int kp = idx >> 5, q = idx & 31;
            cp16(bb + (kp * BSTR + 4 * q) * 4, src + (size_t)kp * N_DIM + 4 * q);
        }
    };

    issue(0, 0); CP_COMMIT();
    issue(1, 1); CP_COMMIT();

    for (int c = 0; c < NCHUNK; ++c) {
        CP_WAIT(1);
        __syncthreads();
        if (c + 2 < NCHUNK) issue(c + 2, (c + 2) % NSTAGE);
        CP_COMMIT();

        const uint32_t* A = gw + (c % NSTAGE) * STAGE_WORDS;
        const uint32_t* B = A + A_STAGE;
#pragma unroll
        for (int s = 0; s < 2; ++s) {
            uint32_t a[4][4];
#pragma unroll
            for (int mt = 0; mt < 4; ++mt) {
                const int row = (m0w + 16 * mt + g) * ASTR;
                a[mt][0] = A[row + 8 * s + tig];
                a[mt][1] = A[row + 8 * ASTR + 8 * s + tig];
                a[mt][2] = A[row + 8 * s + tig + 4];
                a[mt][3] = A[row + 8 * ASTR + 8 * s + tig + 4];
            }
            uint32_t b[4][2];
#pragma unroll
            for (int nt = 0; nt < 4; ++nt) {
                const int col = n0w + 8 * nt + g;
                b[nt][0] = B[(8 * s + tig)     * BSTR + col];
                b[nt][1] = B[(8 * s + tig + 4) * BSTR + col];
            }
#pragma unroll
            for (int mt = 0; mt < 4; ++mt)
#pragma unroll
                for (int nt = 0; nt < 4; ++nt)
                    mma_f16(acc[mt][nt], a[mt][0], a[mt][1], a[mt][2], a[mt][3],
                            b[nt][0], b[nt][1]);
        }
    }
    __syncthreads();   // all mainloop reads done before table bufs overwrite smem

    // ---- table accumulation: 30 features, 2 cp.async buffers ----
    auto issueT = [&](int f, int st) {
        const bool tag = (f < 18);
        const int nv    = tag ? 48 : 40;
        const int tbase = tag ? f * 48 : 864 + (f - 18) * 40;
        const int tot   = nv * 32;   // float4 per slice
        const uint32_t db = t_u32 + st * TWORDS * 4;
        for (int i = t; i < tot; i += THREADS) {
            const int v = i >> 5, q = i & 31;
            cp16(db + (v * TSTR + 4 * q) * 4,
                 g_T + (size_t)(tbase + v) * N_DIM + n0 + 4 * q);
        }
    };

    issueT(0, 0); CP_COMMIT();
    issueT(1, 1); CP_COMMIT();
    int tb = 0;
    for (int f = 0; f < 30; ++f) {
        CP_WAIT(1);
        __syncthreads();

        const float* T = Tun + tb * TWORDS;
        const int fc = 18 + f;
#pragma unroll
        for (int mt = 0; mt < 4; ++mt) {
            const int r0  = m0w + 16 * mt + g;
            const int id0 = ids[r0 * 48 + fc];
            const int id1 = ids[(r0 + 8) * 48 + fc];
            const float* t0 = T + id0 * TSTR + n0w;
            const float* t1 = T + id1 * TSTR + n0w;
#pragma unroll
            for (int nt = 0; nt < 4; ++nt) {
                const float2 v0 = *(const float2*)&t0[8 * nt + 2 * tig];
                const float2 v1 = *(const float2*)&t1[8 * nt + 2 * tig];
                acc[mt][nt][0] += v0.x;  acc[mt][nt][1] += v0.y;
                acc[mt][nt][2] += v1.x;  acc[mt][nt][3] += v1.y;
            }
        }
        __syncthreads();
        if (f + 2 < 30) issueT(f + 2, tb);
        CP_COMMIT();
        tb ^= 1;
    }

    // ---- epilogue: bias + relu + partial dot with W_o slice ----
    float p[4][2][3];
#pragma unroll
    for (int mt = 0; mt < 4; ++mt)
#pragma unroll
        for (int h = 0; h < 2; ++h)
#pragma unroll
            for (int cc = 0; cc < 3; ++cc) p[mt][h][cc] = 0.0f;

#pragma unroll
    for (int nt = 0; nt < 4; ++nt) {
        const int colq = n0w + 8 * nt + 2 * tig;
        const float w00 = wo[colq * 3 + 0], w01 = wo[colq * 3 + 1], w02 = wo[colq * 3 + 2];
        const float w10 = wo[colq * 3 + 3], w11 = wo[colq * 3 + 4], w12 = wo[colq * 3 + 5];
        const float2 bb = *(const float2*)&bh[n0 + colq];
#pragma unroll
        for (int mt = 0; mt < 4; ++mt) {
            float v0 = acc[mt][nt][0] + bb.x;
            float v1 = acc[mt][nt][1] + bb.y;
            float v2 = acc[mt][nt][2] + bb.x;
            float v3 = acc[mt][nt][3] + bb.y;
            v0 = v0 > 0.f ? v0 : 0.f;  v1 = v1 > 0.f ? v1 : 0.f;
            v2 = v2 > 0.f ? v2 : 0.f;  v3 = v3 > 0.f ? v3 : 0.f;
            p[mt][0][0] += v0 * w00 + v1 * w10;
            p[mt][0][1] += v0 * w01 + v1 * w11;
            p[mt][0][2] += v0 * w02 + v1 * w12;
            p[mt][1][0] += v2 * w00 + v3 * w10;
            p[mt][1][1] += v2 * w01 + v3 * w11;
            p[mt][1][2] += v2 * w02 + v3 * w12;
        }
    }
#pragma unroll
    for (int mt = 0; mt < 4; ++mt)
#pragma unroll
        for (int h = 0; h < 2; ++h)
#pragma unroll
            for (int cc = 0; cc < 3; ++cc) {
                float x = p[mt][h][cc];
                x += __shfl_xor_sync(0xffffffffu, x, 1);
                x += __shfl_xor_sync(0xffffffffu, x, 2);
                p[mt][h][cc] = x;
            }
    if (tig == 0) {
        const int slot = blockIdx.x * 4 + wn;
#pragma unroll
        for (int mt = 0; mt < 4; ++mt)
#pragma unroll
            for (int h = 0; h < 2; ++h) {
                const int row = m_blk + m0w + 16 * mt + g + 8 * h;
                float* dst = g_part + ((size_t)slot * B_DIM + row) * 3;
                dst[0] = p[mt][h][0];
                dst[1] = p[mt][h][1];
                dst[2] = p[mt][h][2];
            }
    }
}

// ---------------------------------------------------------------------------
// Final reduce: out[row] = sum_slots g_part + b_o
// ---------------------------------------------------------------------------
__global__ __launch_bounds__(256)
void reduce_out(const float* __restrict__ bo, float* __restrict__ out)
{
    const int row = blockIdx.x * 256 + threadIdx.x;
    float s0 = bo[0], s1 = bo[1], s2 = bo[2];
#pragma unroll
    for (int sl = 0; sl < 32; ++sl) {
        const float* p = g_part + ((size_t)sl * B_DIM + row) * 3;
        s0 += p[0]; s1 += p[1]; s2 += p[2];
    }
    out[row * 3 + 0] = s0;
    out[row * 3 + 1] = s1;
    out[row * 3 + 2] = s2;
}

extern "C" void kernel_launch(void* const* d_in, const int* in_sizes, int n_in,
                              void* d_out, int out_size)
{
    const int*   wid  = (const int*)d_in[0];
    const int*   tgid = (const int*)d_in[1];
    const int*   did  = (const int*)d_in[2];
    const float* wemb = (const float*)d_in[3];
    const float* temb = (const float*)d_in[4];
    const float* demb = (const float*)d_in[5];
    const float* Wh   = (const float*)d_in[6];
    const float* bh   = (const float*)d_in[7];
    const float* Wo   = (const float*)d_in[8];
    const float* bo   = (const float*)d_in[9];
    float* out = (float*)d_out;

    cudaFuncSetAttribute(build_tables,
                         cudaFuncAttributeMaxDynamicSharedMemorySize, 73728);
    cudaFuncSetAttribute(gemm1_mma,
                         cudaFuncAttributeMaxDynamicSharedMemorySize, SMEM_BYTES);

    pack_e16<<<(N_WORD * 32 + 255) / 256, 256>>>(wemb);
    pack_whp<<<1152 * N_DIM / 256, 256>>>(Wh);
    build_tables<<<dim3(30, 8, 3), 256, 73728>>>(temb, demb, Wh);

    gemm1_mma<<<dim3(N_DIM / BN, B_DIM / BM), THREADS, SMEM_BYTES>>>(
        wid, tgid, did, bh, Wo);

    reduce_out<<<B_DIM / 256, 256>>>(bo, out);
}

// round 8
// speedup vs baseline: 9.4067x; 1.0949x over previous
#include <cuda_runtime.h>
#include <cuda_fp16.h>
#include <cstdint>

#define B_DIM   16384
#define N_DIM   1024
#define EMB     128
#define N_WORD  100000

#define BM 128
#define BN 128
#define NCHUNK 72            // word slice K = 2304 = 72 x 32
#define THREADS 256
#define NSTAGE 4

#define ASTR 20              // A smem row stride (uint32 words): 16 kp + 4 pad
#define BSTR 20              // B smem row stride (n-major): 16 kp + 4 pad
#define A_STAGE 2560         // 128 * 20
#define B_STAGE 2560
#define STAGE_BYTES 20480    // (A_STAGE + B_STAGE) * 4

#define IDS_W_BYTES  9216    // 128 x 18 int32
#define IDS_TD_BYTES 4096    // 128 x 32 int8
#define IDS_BYTES    13312
#define UNION_BYTES  (NSTAGE * STAGE_BYTES)      // 81920
#define WO_OFF       (IDS_BYTES + UNION_BYTES)   // 95232
#define SMEM_BYTES   (WO_OFF + 2048)             // 97280

#define TSTR   132
#define TWORDS (48 * TSTR)   // 6336 floats = 25344 B per table buffer

// ---- device scratch ----
__device__ uint32_t g_Ap[(size_t)N_WORD * 64];      // word emb, half2 k-pairs
__device__ uint32_t g_Bp2[(size_t)N_DIM * 1152];    // word W_h slice, n-major half2 k-pairs
__device__ float    g_T[(size_t)1344 * N_DIM];      // tag/deprel tables (fp32)
__device__ float    g_part[(size_t)32 * B_DIM * 3]; // partial out dots

// ---- helpers ----
__device__ __forceinline__ uint32_t smem_u32(const void* p) {
    uint32_t a;
    asm("{ .reg .u64 t; cvta.to.shared.u64 t, %1; cvt.u32.u64 %0, t; }" : "=r"(a) : "l"(p));
    return a;
}
__device__ __forceinline__ void cp16(uint32_t dst, const void* src) {
    asm volatile("cp.async.cg.shared.global [%0], [%1], 16;" :: "r"(dst), "l"(src) : "memory");
}
#define CP_COMMIT() asm volatile("cp.async.commit_group;" ::: "memory")
#define CP_WAIT(n)  asm volatile("cp.async.wait_group %0;" :: "n"(n) : "memory")

__device__ __forceinline__ uint32_t pack2(float a, float b) {
    __half2 h = __floats2half2_rn(a, b);
    return *(uint32_t*)&h;
}
__device__ __forceinline__ void ldsm4(uint32_t r[4], uint32_t addr) {
    asm volatile("ldmatrix.sync.aligned.m8n8.x4.shared.b16 {%0,%1,%2,%3}, [%4];"
                 : "=r"(r[0]), "=r"(r[1]), "=r"(r[2]), "=r"(r[3]) : "r"(addr));
}
__device__ __forceinline__ void mma_f16(float c[4], uint32_t a0, uint32_t a1,
                                        uint32_t a2, uint32_t a3,
                                        uint32_t b0, uint32_t b1) {
    asm volatile(
        "mma.sync.aligned.m16n8k16.row.col.f32.f16.f16.f32 "
        "{%0,%1,%2,%3},{%4,%5,%6,%7},{%8,%9},{%0,%1,%2,%3};"
        : "+f"(c[0]), "+f"(c[1]), "+f"(c[2]), "+f"(c[3])
        : "r"(a0), "r"(a1), "r"(a2), "r"(a3), "r"(b0), "r"(b1));
}

// ---------------------------------------------------------------------------
// Prep kernels
// ---------------------------------------------------------------------------
__global__ void pack_e16(const float* __restrict__ wemb)
{
    const size_t i = (size_t)blockIdx.x * 256 + threadIdx.x;   // float4 index
    if (i >= (size_t)N_WORD * 32) return;
    const float4 v = ((const float4*)wemb)[i];
    *(uint2*)&g_Ap[2 * i] = make_uint2(pack2(v.x, v.y), pack2(v.z, v.w));
}

// n-major pack via smem transpose: g_Bp2[n][kp] = pack2(Wh[2kp][n], Wh[2kp+1][n])
__global__ void pack_whp(const float* __restrict__ Wh)
{
    __shared__ float sm[128][65];
    const int t  = threadIdx.x;
    const int kb = blockIdx.x;   // 18 tiles of 64 kp (128 k rows)
    const int nb = blockIdx.y;   // 16 tiles of 64 n
#pragma unroll
    for (int i = 0; i < 32; ++i) {
        const int idx = t + 256 * i;
        const int r = idx >> 6, c = idx & 63;
        sm[r][c] = Wh[(size_t)(kb * 128 + r) * N_DIM + nb * 64 + c];
    }
    __syncthreads();
#pragma unroll
    for (int i = 0; i < 16; ++i) {
        const int idx = t + 256 * i;
        const int n = idx >> 6, kp = idx & 63;
        g_Bp2[(size_t)(nb * 64 + n) * 1152 + kb * 64 + kp] =
            pack2(sm[2 * kp][n], sm[2 * kp + 1][n]);
    }
}

// T[(f,v)][n] = sum_k E[v][k] * Wh[wrow0_f + k][n]  (exact fp32)
__global__ void build_tables(const float* __restrict__ temb,
                             const float* __restrict__ demb,
                             const float* __restrict__ Wh)
{
    extern __shared__ float bs[];
    float* Ws = bs;            // [128][128]
    float* es = bs + 16384;    // [16][128]

    const int f = blockIdx.x, ct = blockIdx.y, z = blockIdx.z;
    const int t = threadIdx.x;
    const bool tag = (f < 18);
    const int nv    = tag ? 48 : 40;
    const int wrow0 = (tag ? (18 + f) : (36 + (f - 18))) * EMB;
    const int tbase = tag ? f * 48 : 864 + (f - 18) * 40;
    const float* E  = tag ? temb : demb;

    for (int i = t; i < 16384; i += 256) {
        const int k = i >> 7, c = i & 127;
        Ws[i] = Wh[(size_t)(wrow0 + k) * N_DIM + ct * 128 + c];
    }
    for (int i = t; i < 2048; i += 256) {
        const int v = z * 16 + (i >> 7), c = i & 127;
        es[i] = (v < nv) ? E[v * EMB + c] : 0.0f;
    }
    __syncthreads();

    const int c  = t & 127;
    const int vl = t >> 7;
    float s[8];
#pragma unroll
    for (int j = 0; j < 8; ++j) s[j] = 0.0f;
    for (int k = 0; k < 128; ++k) {
        const float wv = Ws[k * 128 + c];
#pragma unroll
        for (int j = 0; j < 8; ++j)
            s[j] = fmaf(es[(vl + 2 * j) * 128 + k], wv, s[j]);
    }
#pragma unroll
    for (int j = 0; j < 8; ++j) {
        const int v = z * 16 + vl + 2 * j;
        if (v < nv) g_T[(size_t)(tbase + v) * N_DIM + ct * 128 + c] = s[j];
    }
}

// ---------------------------------------------------------------------------
// Fused GEMM1 + epilogue dot
// ---------------------------------------------------------------------------
__global__ __launch_bounds__(THREADS, 2)
void gemm1_mma(const int* __restrict__ wid, const int* __restrict__ tgid,
               const int* __restrict__ did,
               const float* __restrict__ bh, const float* __restrict__ Wo)
{
    extern __shared__ char sm[];
    int*   ids_w  = (int*)sm;                         // [128][18]
    char*  ids_td = (char*)(sm + IDS_W_BYTES);        // [128][32]
    float* Tun    = (float*)(sm + IDS_BYTES);         // table bufs (union w/ gemm)
    float* wo     = (float*)(sm + WO_OFF);

    const int t    = threadIdx.x;
    const int lane = t & 31;
    const int w    = t >> 5;
    const int g    = lane >> 2;
    const int tig  = lane & 3;
    const int wm   = w & 1;
    const int wn   = w >> 1;
    const int m0w  = wm * 64;
    const int n0w  = wn * 32;
    const int m_blk = blockIdx.y * BM;
    const int n0    = blockIdx.x * BN;

    const uint32_t sbase  = smem_u32(sm);
    const uint32_t gw_u32 = sbase + IDS_BYTES;
    const uint32_t t_u32  = sbase + IDS_BYTES;

    for (int i = t; i < 128 * 18; i += THREADS) {
        const int row = i / 18, f = i - row * 18;
        ids_w[row * 18 + f] = wid[(m_blk + row) * 18 + f];
    }
    for (int i = t; i < 128 * 30; i += THREADS) {
        const int row = i / 30, f = i - row * 30;
        const int v = (f < 18) ? tgid[(m_blk + row) * 18 + f]
                               : did [(m_blk + row) * 12 + (f - 18)];
        ids_td[row * 32 + f] = (char)v;
    }
    for (int i = t; i < 384; i += THREADS)
        wo[i] = Wo[(size_t)n0 * 3 + i];
    __syncthreads();

    float acc[4][4][4];
#pragma unroll
    for (int i = 0; i < 4; ++i)
#pragma unroll
        for (int j = 0; j < 4; ++j)
#pragma unroll
            for (int q = 0; q < 4; ++q) acc[i][j][q] = 0.0f;

    // ldmatrix per-lane byte offsets
    uint32_t aoff[4], boff[2];
    {
        const int arow = m0w + (lane & 15);
        const int awrd = 4 * (lane >> 4);
#pragma unroll
        for (int mt = 0; mt < 4; ++mt)
            aoff[mt] = (uint32_t)(((arow + 16 * mt) * ASTR + awrd) * 4);
        const int brow = n0w + (lane & 7) + 8 * (lane >> 4);
        const int bwrd = 4 * ((lane >> 3) & 1);
#pragma unroll
        for (int p = 0; p < 2; ++p)
            boff[p] = (uint32_t)(((brow + 16 * p) * BSTR + bwrd) * 4 + A_STAGE * 4);
    }

    auto issue = [&](int c, int st) {
        const int f   = c >> 2;
        const int kpo = (c & 3) * 16;
        const uint32_t ab = gw_u32 + st * STAGE_BYTES;
        const uint32_t bb = ab + A_STAGE * 4;
#pragma unroll
        for (int r = 0; r < 2; ++r) {
            const int idx = t + 256 * r;
            const int row = idx >> 2, q = idx & 3;
            const int id  = ids_w[row * 18 + f];
            cp16(ab + (row * ASTR + 4 * q) * 4, g_Ap + (size_t)id * 64 + kpo + 4 * q);
        }
#pragma unroll
        for (int r = 0; r < 2; ++r) {
            const int idx = t + 256 * r;
            const int row = idx >> 2, q = idx & 3;
            cp16(bb + (row * BSTR + 4 * q) * 4,
                 g_Bp2 + (size_t)(n0 + row) * 1152 + c * 16 + 4 * q);
        }
    };

    issue(0, 0); CP_COMMIT();
    issue(1, 1); CP_COMMIT();
    issue(2, 2); CP_COMMIT();

    for (int c = 0; c < NCHUNK; ++c) {
        CP_WAIT(2);
        __syncthreads();
        if (c + 3 < NCHUNK) issue(c + 3, (c + 3) & 3);
        CP_COMMIT();

        const uint32_t st = gw_u32 + (c & 3) * STAGE_BYTES;
#pragma unroll
        for (int s = 0; s < 2; ++s) {
            uint32_t a[4][4], b[2][4];
#pragma unroll
            for (int mt = 0; mt < 4; ++mt)
                ldsm4(a[mt], st + aoff[mt] + s * 32);
#pragma unroll
            for (int p = 0; p < 2; ++p)
                ldsm4(b[p], st + boff[p] + s * 32);
#pragma unroll
            for (int mt = 0; mt < 4; ++mt) {
                mma_f16(acc[mt][0], a[mt][0], a[mt][1], a[mt][2], a[mt][3], b[0][0], b[0][1]);
                mma_f16(acc[mt][1], a[mt][0], a[mt][1], a[mt][2], a[mt][3], b[0][2], b[0][3]);
                mma_f16(acc[mt][2], a[mt][0], a[mt][1], a[mt][2], a[mt][3], b[1][0], b[1][1]);
                mma_f16(acc[mt][3], a[mt][0], a[mt][1], a[mt][2], a[mt][3], b[1][2], b[1][3]);
            }
        }
    }
    __syncthreads();   // mainloop smem reads done before table bufs overwrite

    // ---- table accumulation: 30 features, 2 cp.async buffers ----
    auto issueT = [&](int f, int st) {
        const bool tag = (f < 18);
        const int nv    = tag ? 48 : 40;
        const int tbase = tag ? f * 48 : 864 + (f - 18) * 40;
        const int tot   = nv * 32;
        const uint32_t db = t_u32 + st * TWORDS * 4;
        for (int i = t; i < tot; i += THREADS) {
            const int v = i >> 5, q = i & 31;
            cp16(db + (v * TSTR + 4 * q) * 4,
                 g_T + (size_t)(tbase + v) * N_DIM + n0 + 4 * q);
        }
    };

    issueT(0, 0); CP_COMMIT();
    issueT(1, 1); CP_COMMIT();
    int tb = 0;
    for (int f = 0; f < 30; ++f) {
        CP_WAIT(1);
        __syncthreads();

        const float* T = Tun + tb * TWORDS;
#pragma unroll
        for (int mt = 0; mt < 4; ++mt) {
            const int r0  = m0w + 16 * mt + g;
            const int id0 = ids_td[r0 * 32 + f];
            const int id1 = ids_td[(r0 + 8) * 32 + f];
            const float* t0 = T + id0 * TSTR + n0w;
            const float* t1 = T + id1 * TSTR + n0w;
#pragma unroll
            for (int nt = 0; nt < 4; ++nt) {
                const float2 v0 = *(const float2*)&t0[8 * nt + 2 * tig];
                const float2 v1 = *(const float2*)&t1[8 * nt + 2 * tig];
                acc[mt][nt][0] += v0.x;  acc[mt][nt][1] += v0.y;
                acc[mt][nt][2] += v1.x;  acc[mt][nt][3] += v1.y;
            }
        }
        __syncthreads();
        if (f + 2 < 30) issueT(f + 2, tb);
        CP_COMMIT();
        tb ^= 1;
    }

    // ---- epilogue: bias + relu + partial dot with W_o slice ----
    float p[4][2][3];
#pragma unroll
    for (int mt = 0; mt < 4; ++mt)
#pragma unroll
        for (int h = 0; h < 2; ++h)
#pragma unroll
            for (int cc = 0; cc < 3; ++cc) p[mt][h][cc] = 0.0f;

#pragma unroll
    for (int nt = 0; nt < 4; ++nt) {
        const int colq = n0w + 8 * nt + 2 * tig;
        const float w00 = wo[colq * 3 + 0], w01 = wo[colq * 3 + 1], w02 = wo[colq * 3 + 2];
        const float w10 = wo[colq * 3 + 3], w11 = wo[colq * 3 + 4], w12 = wo[colq * 3 + 5];
        const float2 bb = *(const float2*)&bh[n0 + colq];
#pragma unroll
        for (int mt = 0; mt < 4; ++mt) {
            float v0 = acc[mt][nt][0] + bb.x;
            float v1 = acc[mt][nt][1] + bb.y;
            float v2 = acc[mt][nt][2] + bb.x;
            float v3 = acc[mt][nt][3] + bb.y;
            v0 = v0 > 0.f ? v0 : 0.f;  v1 = v1 > 0.f ? v1 : 0.f;
            v2 = v2 > 0.f ? v2 : 0.f;  v3 = v3 > 0.f ? v3 : 0.f;
            p[mt][0][0] += v0 * w00 + v1 * w10;
            p[mt][0][1] += v0 * w01 + v1 * w11;
            p[mt][0][2] += v0 * w02 + v1 * w12;
            p[mt][1][0] += v2 * w00 + v3 * w10;
            p[mt][1][1] += v2 * w01 + v3 * w11;
            p[mt][1][2] += v2 * w02 + v3 * w12;
        }
    }
#pragma unroll
    for (int mt = 0; mt < 4; ++mt)
#pragma unroll
        for (int h = 0; h < 2; ++h)
#pragma unroll
            for (int cc = 0; cc < 3; ++cc) {
                float x = p[mt][h][cc];
                x += __shfl_xor_sync(0xffffffffu, x, 1);
                x += __shfl_xor_sync(0xffffffffu, x, 2);
                p[mt][h][cc] = x;
            }
    if (tig == 0) {
        const int slot = blockIdx.x * 4 + wn;
#pragma unroll
        for (int mt = 0; mt < 4; ++mt)
#pragma unroll
            for (int h = 0; h < 2; ++h) {
                const int row = m_blk + m0w + 16 * mt + g + 8 * h;
                float* dst = g_part + ((size_t)slot * B_DIM + row) * 3;
                dst[0] = p[mt][h][0];
                dst[1] = p[mt][h][1];
                dst[2] = p[mt][h][2];
            }
    }
}

// ---------------------------------------------------------------------------
// Final reduce: out[row] = sum_slots g_part + b_o
// ---------------------------------------------------------------------------
__global__ __launch_bounds__(256)
void reduce_out(const float* __restrict__ bo, float* __restrict__ out)
{
    const int row = blockIdx.x * 256 + threadIdx.x;
    float s0 = bo[0], s1 = bo[1], s2 = bo[2];
#pragma unroll
    for (int sl = 0; sl < 32; ++sl) {
        const float* p = g_part + ((size_t)sl * B_DIM + row) * 3;
        s0 += p[0]; s1 += p[1]; s2 += p[2];
    }
    out[row * 3 + 0] = s0;
    out[row * 3 + 1] = s1;
    out[row * 3 + 2] = s2;
}

extern "C" void kernel_launch(void* const* d_in, const int* in_sizes, int n_in,
                              void* d_out, int out_size)
{
    const int*   wid  = (const int*)d_in[0];
    const int*   tgid = (const int*)d_in[1];
    const int*   did  = (const int*)d_in[2];
    const float* wemb = (const float*)d_in[3];
    const float* temb = (const float*)d_in[4];
    const float* demb = (const float*)d_in[5];
    const float* Wh   = (const float*)d_in[6];
    const float* bh   = (const float*)d_in[7];
    const float* Wo   = (const float*)d_in[8];
    const float* bo   = (const float*)d_in[9];
    float* out = (float*)d_out;

    cudaFuncSetAttribute(build_tables,
                         cudaFuncAttributeMaxDynamicSharedMemorySize, 73728);
    cudaFuncSetAttribute(gemm1_mma,
                         cudaFuncAttributeMaxDynamicSharedMemorySize, SMEM_BYTES);

    pack_e16<<<(N_WORD * 32 + 255) / 256, 256>>>(wemb);
    pack_whp<<<dim3(18, 16), 256>>>(Wh);
    build_tables<<<dim3(30, 8, 3), 256, 73728>>>(temb, demb, Wh);

    gemm1_mma<<<dim3(N_DIM / BN, B_DIM / BM), THREADS, SMEM_BYTES>>>(
        wid, tgid, did, bh, Wo);

    reduce_out<<<B_DIM / 256, 256>>>(bo, out);
}